// round 1
// baseline (speedup 1.0000x reference)
#include <cuda_runtime.h>
#include <math.h>

// Problem constants
constexpr int BB  = 256;   // batch
constexpr int THN = 32;    // history steps
constexpr int TFN = 16;    // future steps
constexpr int SS  = 512;   // state size
constexpr int AS  = 128;   // action size
constexpr int FS  = 1024;  // feature size
constexpr int G3  = 3072;  // 3*F (gates)
constexpr int TT  = 65;    // prefix length 2*TH+1

// Scratch (device globals; no allocation allowed)
__device__ float g_xs  [TT * BB * FS];   // prefix inputs, [t][b][f]
__device__ float g_seq0[TT * BB * FS];   // layer-0 outputs over prefix
__device__ float g_gi  [TT * BB * G3];   // batched input gates
__device__ float g_gh  [BB * G3];        // per-step hidden gates
__device__ float g_gif [BB * G3];        // per-step input gates (future)
__device__ float g_h0  [BB * FS];
__device__ float g_h1  [BB * FS];
__device__ float g_x   [BB * FS];        // current cell input embedding
__device__ float g_s   [BB * SS];        // predicted state

// ---------------------------------------------------------------------------
// Tiled NT GEMM: C[m,n] = act( sum_k A[m,k] * W[n,k] + bias[n] )
// A: [M,K] rows stride lda; W: [N,K] rows stride ldw (PyTorch weight layout).
// rowmap: 0 identity; 1/2 interleave into xs (s_emb even t, a_emb odd t).
// Optional second output C2 with stride ldc2 (for writing d_out + scratch).
// All M,N multiples of 64; all K multiples of 16; all strides multiples of 4.
// ---------------------------------------------------------------------------
#define BM 64
#define BN 64
#define BK 16

__global__ void __launch_bounds__(256) gemm_nt(
    const float* __restrict__ A, int lda,
    const float* __restrict__ W, int ldw,
    const float* __restrict__ bias,
    float* __restrict__ C, int ldc,
    float* __restrict__ C2, int ldc2,
    int K, int act, int rowmap)
{
    __shared__ float As[BK][BM];
    __shared__ float Bs[BK][BN];

    const int tid  = threadIdx.x;
    const int row0 = blockIdx.y * BM;
    const int col0 = blockIdx.x * BN;

    const int lr = tid >> 2;          // 0..63
    const int lc = (tid & 3) * 4;     // 0,4,8,12
    const float* Arow = A + (size_t)(row0 + lr) * lda + lc;
    const float* Wrow = W + (size_t)(col0 + lr) * ldw + lc;

    const int ty = tid >> 4;          // 0..15
    const int tx = tid & 15;          // 0..15

    float acc[4][4] = {};

    for (int k0 = 0; k0 < K; k0 += BK) {
        float4 av = *(const float4*)(Arow + k0);
        float4 wv = *(const float4*)(Wrow + k0);
        __syncthreads();
        As[lc + 0][lr] = av.x; As[lc + 1][lr] = av.y;
        As[lc + 2][lr] = av.z; As[lc + 3][lr] = av.w;
        Bs[lc + 0][lr] = wv.x; Bs[lc + 1][lr] = wv.y;
        Bs[lc + 2][lr] = wv.z; Bs[lc + 3][lr] = wv.w;
        __syncthreads();
        #pragma unroll
        for (int k = 0; k < BK; k++) {
            float4 a = *(const float4*)&As[k][ty * 4];
            float4 b = *(const float4*)&Bs[k][tx * 4];
            acc[0][0] += a.x * b.x; acc[0][1] += a.x * b.y;
            acc[0][2] += a.x * b.z; acc[0][3] += a.x * b.w;
            acc[1][0] += a.y * b.x; acc[1][1] += a.y * b.y;
            acc[1][2] += a.y * b.z; acc[1][3] += a.y * b.w;
            acc[2][0] += a.z * b.x; acc[2][1] += a.z * b.y;
            acc[2][2] += a.z * b.z; acc[2][3] += a.z * b.w;
            acc[3][0] += a.w * b.x; acc[3][1] += a.w * b.y;
            acc[3][2] += a.w * b.z; acc[3][3] += a.w * b.w;
        }
    }

    #pragma unroll
    for (int i = 0; i < 4; i++) {
        int m = row0 + ty * 4 + i;
        int mp;
        if (rowmap == 1)      mp = ((m & 31) << 1) * BB + (m >> 5);
        else if (rowmap == 2) mp = (((m & 31) << 1) + 1) * BB + (m >> 5);
        else                  mp = m;
        #pragma unroll
        for (int j = 0; j < 4; j++) {
            int n = col0 + tx * 4 + j;
            float v = acc[i][j] + bias[n];
            if (act == 1)      v = tanhf(v);
            else if (act == 2) v = 1.0f / (1.0f + expf(-v));
            C[(size_t)mp * ldc + n] = v;
            if (C2) C2[(size_t)m * ldc2 + n] = v;
        }
    }
}

// ---------------------------------------------------------------------------
// GRU gate combine: h <- (1-z)*n + z*h ; optional copy of new h to seq_out
// gi, gh: [256, 3072] gate pre-activations (r,z,n); h: [256,1024] in/out
// ---------------------------------------------------------------------------
__global__ void gru_combine(const float* __restrict__ gi,
                            const float* __restrict__ gh,
                            float* __restrict__ h,
                            float* __restrict__ seq_out)
{
    int idx = blockIdx.x * blockDim.x + threadIdx.x;
    if (idx >= BB * FS) return;
    int m = idx >> 10;       // FS = 1024
    int j = idx & (FS - 1);
    size_t base = (size_t)m * G3 + j;
    float ir = gi[base], iz = gi[base + FS], in = gi[base + 2 * FS];
    float hr = gh[base], hz = gh[base + FS], hn = gh[base + 2 * FS];
    float r = 1.0f / (1.0f + expf(-(ir + hr)));
    float z = 1.0f / (1.0f + expf(-(iz + hz)));
    float n = tanhf(in + r * hn);
    float hv = (1.0f - z) * n + z * h[idx];
    h[idx] = hv;
    if (seq_out) seq_out[idx] = hv;
}

// ---------------------------------------------------------------------------
// Reward head: out_r[b*TFN + t] = sigmoid(h1[b] . Wr + br). One warp per row.
// ---------------------------------------------------------------------------
__global__ void reward_kernel(const float* __restrict__ h1,
                              const float* __restrict__ Wr,
                              const float* __restrict__ br,
                              float* __restrict__ out_r, int t)
{
    int g    = blockIdx.x * blockDim.x + threadIdx.x;
    int warp = g >> 5;
    int lane = g & 31;
    if (warp >= BB) return;
    const float* hr = h1 + (size_t)warp * FS;
    float s = 0.0f;
    #pragma unroll 8
    for (int k = lane; k < FS; k += 32) s += hr[k] * Wr[k];
    #pragma unroll
    for (int o = 16; o; o >>= 1) s += __shfl_xor_sync(0xFFFFFFFFu, s, o);
    if (lane == 0)
        out_r[warp * TFN + t] = 1.0f / (1.0f + expf(-(s + br[0])));
}

__global__ void zero_h(float* __restrict__ a, float* __restrict__ b)
{
    int idx = blockIdx.x * blockDim.x + threadIdx.x;
    if (idx < BB * FS) { a[idx] = 0.0f; b[idx] = 0.0f; }
}

// ---------------------------------------------------------------------------
// Host orchestration
// ---------------------------------------------------------------------------
static inline void gemm(const float* A, int lda, const float* W, int ldw,
                        const float* bias, float* C, int ldc,
                        float* C2, int ldc2, int M, int N, int K,
                        int act, int rowmap)
{
    dim3 grid(N / BN, M / BM);
    gemm_nt<<<grid, 256>>>(A, lda, W, ldw, bias, C, ldc, C2, ldc2, K, act, rowmap);
}

extern "C" void kernel_launch(void* const* d_in, const int* in_sizes, int n_in,
                              void* d_out, int out_size)
{
    const float* history_s = (const float*)d_in[0];   // [256,32,512]
    const float* history_a = (const float*)d_in[1];   // [256,32,128]
    const float* present_s = (const float*)d_in[2];   // [256,512]
    const float* future_a  = (const float*)d_in[3];   // [256,16,128]
    const float* Ws  = (const float*)d_in[4];         // [1024,512]
    const float* bs  = (const float*)d_in[5];
    const float* Wa  = (const float*)d_in[6];         // [1024,128]
    const float* ba  = (const float*)d_in[7];
    const float* Wih = (const float*)d_in[8];         // [2,3072,1024]
    const float* Whh = (const float*)d_in[9];
    const float* bih = (const float*)d_in[10];        // [2,3072]
    const float* bhh = (const float*)d_in[11];
    const float* Wr  = (const float*)d_in[12];        // [1,1024]
    const float* br  = (const float*)d_in[13];
    const float* Ws2 = (const float*)d_in[14];        // [512,1024]
    const float* bs2 = (const float*)d_in[15];

    float* out_r = (float*)d_out;                     // [256,16]
    float* out_s = (float*)d_out + BB * TFN;          // [256,16,512]

    float *xs, *seq0, *gi, *gh, *gif, *h0, *h1, *x, *sbuf;
    cudaGetSymbolAddress((void**)&xs,   g_xs);
    cudaGetSymbolAddress((void**)&seq0, g_seq0);
    cudaGetSymbolAddress((void**)&gi,   g_gi);
    cudaGetSymbolAddress((void**)&gh,   g_gh);
    cudaGetSymbolAddress((void**)&gif,  g_gif);
    cudaGetSymbolAddress((void**)&h0,   g_h0);
    cudaGetSymbolAddress((void**)&h1,   g_h1);
    cudaGetSymbolAddress((void**)&x,    g_x);
    cudaGetSymbolAddress((void**)&sbuf, g_s);

    const float* Wih0 = Wih;            const float* Wih1 = Wih + (size_t)G3 * FS;
    const float* Whh0 = Whh;            const float* Whh1 = Whh + (size_t)G3 * FS;
    const float* bih0 = bih;            const float* bih1 = bih + G3;
    const float* bhh0 = bhh;            const float* bhh1 = bhh + G3;

    zero_h<<<(BB * FS + 255) / 256, 256>>>(h0, h1);

    // Prefix input embeddings -> g_xs[t][b][f] (interleaved s/a, present last)
    gemm(history_s, SS, Ws, SS, bs, xs, FS, nullptr, 0, BB * THN, FS, SS, 1, 1);
    gemm(history_a, AS, Wa, AS, ba, xs, FS, nullptr, 0, BB * THN, FS, AS, 1, 2);
    gemm(present_s, SS, Ws, SS, bs, xs + (size_t)(TT - 1) * BB * FS, FS,
         nullptr, 0, BB, FS, SS, 1, 0);

    // Layer 0: batched input gates, then sequential scan
    gemm(xs, FS, Wih0, FS, bih0, gi, G3, nullptr, 0, TT * BB, G3, FS, 0, 0);
    for (int t = 0; t < TT; t++) {
        gemm(h0, FS, Whh0, FS, bhh0, gh, G3, nullptr, 0, BB, G3, FS, 0, 0);
        gru_combine<<<(BB * FS + 255) / 256, 256>>>(
            gi + (size_t)t * BB * G3, gh, h0, seq0 + (size_t)t * BB * FS);
    }

    // Layer 1: batched input gates over layer-0 outputs, then scan
    gemm(seq0, FS, Wih1, FS, bih1, gi, G3, nullptr, 0, TT * BB, G3, FS, 0, 0);
    for (int t = 0; t < TT; t++) {
        gemm(h1, FS, Whh1, FS, bhh1, gh, G3, nullptr, 0, BB, G3, FS, 0, 0);
        gru_combine<<<(BB * FS + 255) / 256, 256>>>(
            gi + (size_t)t * BB * G3, gh, h1, nullptr);
    }

    // Future rollout
    for (int t = 0; t < TFN; t++) {
        // action embedding
        gemm(future_a + (size_t)t * AS, TFN * AS, Wa, AS, ba, x, FS,
             nullptr, 0, BB, FS, AS, 1, 0);
        // cell layer 0 (input x)
        gemm(x,  FS, Wih0, FS, bih0, gif, G3, nullptr, 0, BB, G3, FS, 0, 0);
        gemm(h0, FS, Whh0, FS, bhh0, gh,  G3, nullptr, 0, BB, G3, FS, 0, 0);
        gru_combine<<<(BB * FS + 255) / 256, 256>>>(gif, gh, h0, nullptr);
        // cell layer 1 (input new h0)
        gemm(h0, FS, Wih1, FS, bih1, gif, G3, nullptr, 0, BB, G3, FS, 0, 0);
        gemm(h1, FS, Whh1, FS, bhh1, gh,  G3, nullptr, 0, BB, G3, FS, 0, 0);
        gru_combine<<<(BB * FS + 255) / 256, 256>>>(gif, gh, h1, nullptr);

        // heads: reward + next-state (also scattered into d_out)
        reward_kernel<<<(BB * 32 + 255) / 256, 256>>>(h1, Wr, br, out_r, t);
        gemm(h1, FS, Ws2, FS, bs2, sbuf, SS, out_s + (size_t)t * SS, TFN * SS,
             BB, SS, FS, 1, 0);
        // state embedding feed-back
        gemm(sbuf, SS, Ws, SS, bs, x, FS, nullptr, 0, BB, FS, SS, 1, 0);
        // cell layer 0 (input x2)
        gemm(x,  FS, Wih0, FS, bih0, gif, G3, nullptr, 0, BB, G3, FS, 0, 0);
        gemm(h0, FS, Whh0, FS, bhh0, gh,  G3, nullptr, 0, BB, G3, FS, 0, 0);
        gru_combine<<<(BB * FS + 255) / 256, 256>>>(gif, gh, h0, nullptr);
        // cell layer 1
        gemm(h0, FS, Wih1, FS, bih1, gif, G3, nullptr, 0, BB, G3, FS, 0, 0);
        gemm(h1, FS, Whh1, FS, bhh1, gh,  G3, nullptr, 0, BB, G3, FS, 0, 0);
        gru_combine<<<(BB * FS + 255) / 256, 256>>>(gif, gh, h1, nullptr);
    }
}

// round 5
// speedup vs baseline: 3.1560x; 3.1560x over previous
#include <cuda_runtime.h>
#include <cuda_bf16.h>
#include <cstdint>
#include <math.h>

constexpr int BB  = 256;
constexpr int THN = 32;
constexpr int TFN = 16;
constexpr int SS  = 512;
constexpr int AS  = 128;
constexpr int FS  = 1024;
constexpr int G3  = 3072;
constexpr int TT  = 65;

// ---------------- scratch (device globals; no allocation allowed) ----------
__device__ float g_xs  [TT * BB * FS];
__device__ float g_seq0[TT * BB * FS];
__device__ float g_gi  [TT * BB * G3];
__device__ float g_gh0 [BB * G3];
__device__ float g_gh1 [BB * G3];
__device__ float g_gi1 [BB * G3];
__device__ float g_h0  [BB * FS];
__device__ float g_h1  [BB * FS];
__device__ float g_x   [BB * FS];
__device__ float g_s   [BB * SS];

// split bf16 weights (hi/lo), laid out [N, K] like the fp32 originals
__device__ __nv_bfloat16 g_Ws_hi [FS * SS],     g_Ws_lo [FS * SS];
__device__ __nv_bfloat16 g_Wa_hi [FS * AS],     g_Wa_lo [FS * AS];
__device__ __nv_bfloat16 g_Wih_hi[2 * G3 * FS], g_Wih_lo[2 * G3 * FS];
__device__ __nv_bfloat16 g_Whh_hi[2 * G3 * FS], g_Whh_lo[2 * G3 * FS];
__device__ __nv_bfloat16 g_Ws2_hi[SS * FS],     g_Ws2_lo[SS * FS];

// ---------------- warp MMA helpers (arch-agnostic PTX) ---------------------
__device__ __forceinline__ uint32_t smem_u32(const void* p) {
    uint32_t a;
    asm("{ .reg .u64 t; cvta.to.shared.u64 t, %1; cvt.u32.u64 %0, t; }"
        : "=r"(a) : "l"(p));
    return a;
}

__device__ __forceinline__ void ldmx4(uint32_t* r, uint32_t addr) {
    asm volatile("ldmatrix.sync.aligned.m8n8.x4.shared.b16 {%0,%1,%2,%3}, [%4];"
                 : "=r"(r[0]), "=r"(r[1]), "=r"(r[2]), "=r"(r[3]) : "r"(addr));
}

__device__ __forceinline__ void mma16816(float* d, const uint32_t* a, const uint32_t* b) {
    asm volatile(
        "mma.sync.aligned.m16n8k16.row.col.f32.bf16.bf16.f32 "
        "{%0,%1,%2,%3}, {%4,%5,%6,%7}, {%8,%9}, {%0,%1,%2,%3};"
        : "+f"(d[0]), "+f"(d[1]), "+f"(d[2]), "+f"(d[3])
        : "r"(a[0]), "r"(a[1]), "r"(a[2]), "r"(a[3]), "r"(b[0]), "r"(b[1]));
}

// ---------------- GEMM kernel ----------------------------------------------
// C[m,n] = act( sum_k A[m,k]*W[n,k] + bias[n] ), fp32 A/C, split-bf16 weights.
// 3-pass split MMA: Ahi*Whi + Ahi*Wlo + Alo*Whi, fp32 accumulate.
// Tile 128x128, BK=32, 8 warps (2m x 4n), warp tile 64x32.
struct GTask {
    const float* A; int64_t lda;
    const __nv_bfloat16* Wh; const __nv_bfloat16* Wl;
    const float* bias;
    float* C;  int64_t ldc;
    float* C2; int64_t ldc2;
    int act; int rowmap;
};

// smem: 4 tiles of 128 rows x 80 bytes (32 bf16 + 16B pad) = 10240 B each
constexpr int TROW = 80;
constexpr int OFF_AHI = 0;
constexpr int OFF_ALO = 10240;
constexpr int OFF_WHI = 20480;
constexpr int OFF_WLO = 30720;

__device__ __forceinline__ float act_f(float v, int act) {
    if (act == 1) return tanhf(v);
    if (act == 2) return 1.0f / (1.0f + expf(-v));
    return v;
}

__device__ __forceinline__ void split2(float v, unsigned short& h, unsigned short& l) {
    __nv_bfloat16 b = __float2bfloat16_rn(v);
    h = __bfloat16_as_ushort(b);
    l = __bfloat16_as_ushort(__float2bfloat16_rn(v - __bfloat162float(b)));
}

__global__ void __launch_bounds__(256, 1) mm_kernel(GTask T0, GTask T1, GTask T2, int K)
{
    __shared__ __align__(16) char sm[40960];
    const GTask T = (blockIdx.z == 0) ? T0 : (blockIdx.z == 1 ? T1 : T2);
    const uint32_t sb = smem_u32(sm);
    const int tid  = threadIdx.x;
    const int wid  = tid >> 5, lane = tid & 31;
    const int row0 = blockIdx.y * 128, col0 = blockIdx.x * 128;
    const int m0w  = (wid >> 2) * 64;     // warp m offset (0 or 64)
    const int n0w  = (wid & 3) * 32;      // warp n offset (0,32,64,96)

    // per-lane ldmatrix smem offsets (byte offsets within a tile)
    const uint32_t a_lrow = (uint32_t)(lane & 15);
    const uint32_t a_lcol = (uint32_t)((lane >> 4) * 16);     // bytes
    const uint32_t b_lrow = (uint32_t)((lane & 7) + ((lane >> 4) & 1) * 8);
    const uint32_t b_lcol = (uint32_t)(((lane >> 3) & 1) * 16); // bytes

    float acc[4][4][4];
    #pragma unroll
    for (int i = 0; i < 4; i++)
        #pragma unroll
        for (int j = 0; j < 4; j++)
            #pragma unroll
            for (int q = 0; q < 4; q++) acc[i][j][q] = 0.0f;

    const int NC = K >> 5;   // chunks of 32

    // prefetch registers
    float4 av[4];
    uint4  wh[2], wl[2];

    const int ar   = tid >> 1;            // A row (0..127)
    const int acq  = (tid & 1) * 16;      // A col start (floats)

    // ---- load chunk 0 into regs ----
    {
        const float* Ab = T.A + (size_t)(row0 + ar) * T.lda + acq;
        #pragma unroll
        for (int i = 0; i < 4; i++) av[i] = *(const float4*)(Ab + i * 4);
        #pragma unroll
        for (int i = 0; i < 2; i++) {
            int g = tid + (i << 8);
            int r = g >> 2, part = g & 3;
            const __nv_bfloat16* ph = T.Wh + (size_t)(col0 + r) * K + part * 8;
            const __nv_bfloat16* pl = T.Wl + (size_t)(col0 + r) * K + part * 8;
            wh[i] = *(const uint4*)ph;
            wl[i] = *(const uint4*)pl;
        }
    }

    for (int c = 0; c < NC; c++) {
        __syncthreads();   // smem free (previous compute done)

        // ---- store prefetched regs to smem (split A on the fly) ----
        {
            unsigned short h[16], l[16];
            #pragma unroll
            for (int i = 0; i < 4; i++) {
                split2(av[i].x, h[i*4+0], l[i*4+0]);
                split2(av[i].y, h[i*4+1], l[i*4+1]);
                split2(av[i].z, h[i*4+2], l[i*4+2]);
                split2(av[i].w, h[i*4+3], l[i*4+3]);
            }
            uint32_t off = (uint32_t)(ar * TROW + acq * 2);
            #pragma unroll
            for (int i = 0; i < 2; i++) {
                uint4 hp, lp;
                hp.x = (uint32_t)h[i*8+0] | ((uint32_t)h[i*8+1] << 16);
                hp.y = (uint32_t)h[i*8+2] | ((uint32_t)h[i*8+3] << 16);
                hp.z = (uint32_t)h[i*8+4] | ((uint32_t)h[i*8+5] << 16);
                hp.w = (uint32_t)h[i*8+6] | ((uint32_t)h[i*8+7] << 16);
                lp.x = (uint32_t)l[i*8+0] | ((uint32_t)l[i*8+1] << 16);
                lp.y = (uint32_t)l[i*8+2] | ((uint32_t)l[i*8+3] << 16);
                lp.z = (uint32_t)l[i*8+4] | ((uint32_t)l[i*8+5] << 16);
                lp.w = (uint32_t)l[i*8+6] | ((uint32_t)l[i*8+7] << 16);
                *(uint4*)(sm + OFF_AHI + off + i * 16) = hp;
                *(uint4*)(sm + OFF_ALO + off + i * 16) = lp;
            }
            #pragma unroll
            for (int i = 0; i < 2; i++) {
                int g = tid + (i << 8);
                int r = g >> 2, part = g & 3;
                *(uint4*)(sm + OFF_WHI + r * TROW + part * 16) = wh[i];
                *(uint4*)(sm + OFF_WLO + r * TROW + part * 16) = wl[i];
            }
        }
        __syncthreads();

        // ---- prefetch next chunk's globals (latency hidden behind MMA) ----
        if (c + 1 < NC) {
            int k0 = (c + 1) << 5;
            const float* Ab = T.A + (size_t)(row0 + ar) * T.lda + k0 + acq;
            #pragma unroll
            for (int i = 0; i < 4; i++) av[i] = *(const float4*)(Ab + i * 4);
            #pragma unroll
            for (int i = 0; i < 2; i++) {
                int g = tid + (i << 8);
                int r = g >> 2, part = g & 3;
                wh[i] = *(const uint4*)(T.Wh + (size_t)(col0 + r) * K + k0 + part * 8);
                wl[i] = *(const uint4*)(T.Wl + (size_t)(col0 + r) * K + k0 + part * 8);
            }
        }

        // ---- MMA over the 2 k16 steps of this chunk ----
        #pragma unroll
        for (int ks = 0; ks < 2; ks++) {
            uint32_t Ahi[16], Alo[16], Bhi[8], Blo[8];
            const uint32_t kc = (uint32_t)(ks * 32);  // byte offset of k16
            #pragma unroll
            for (int mt = 0; mt < 4; mt++) {
                uint32_t addr = sb + (uint32_t)((m0w + mt * 16 + a_lrow) * TROW)
                              + kc + a_lcol;
                ldmx4(Ahi + mt * 4, addr + OFF_AHI);
                ldmx4(Alo + mt * 4, addr + OFF_ALO);
            }
            #pragma unroll
            for (int p = 0; p < 2; p++) {
                uint32_t addr = sb + (uint32_t)((n0w + p * 16 + b_lrow) * TROW)
                              + kc + b_lcol;
                ldmx4(Bhi + p * 4, addr + OFF_WHI);
                ldmx4(Blo + p * 4, addr + OFF_WLO);
            }
            #pragma unroll
            for (int mt = 0; mt < 4; mt++) {
                #pragma unroll
                for (int nt = 0; nt < 4; nt++) {
                    const uint32_t* bh = &Bhi[(nt >> 1) * 4 + (nt & 1) * 2];
                    const uint32_t* bl = &Blo[(nt >> 1) * 4 + (nt & 1) * 2];
                    mma16816(acc[mt][nt], Ahi + mt * 4, bh);
                    mma16816(acc[mt][nt], Ahi + mt * 4, bl);
                    mma16816(acc[mt][nt], Alo + mt * 4, bh);
                }
            }
        }
    }

    // ---- epilogue: bias + act + rowmap + optional dual store ----
    const int tq = lane >> 2, tr = lane & 3;
    #pragma unroll
    for (int mt = 0; mt < 4; mt++) {
        #pragma unroll
        for (int half = 0; half < 2; half++) {
            int m = row0 + m0w + mt * 16 + half * 8 + tq;
            int mp;
            if (T.rowmap == 1)      mp = ((m & 31) << 1) * BB + (m >> 5);
            else if (T.rowmap == 2) mp = (((m & 31) << 1) + 1) * BB + (m >> 5);
            else                    mp = m;
            float* Crow  = T.C + (size_t)mp * T.ldc;
            float* C2row = T.C2 ? T.C2 + (size_t)m * T.ldc2 : nullptr;
            #pragma unroll
            for (int nt = 0; nt < 4; nt++) {
                int n = col0 + n0w + nt * 8 + tr * 2;
                float2 bv = *(const float2*)(T.bias + n);
                float2 o;
                o.x = act_f(acc[mt][nt][half * 2 + 0] + bv.x, T.act);
                o.y = act_f(acc[mt][nt][half * 2 + 1] + bv.y, T.act);
                *(float2*)(Crow + n) = o;
                if (C2row) *(float2*)(C2row + n) = o;
            }
        }
    }
}

// ---------------- elementwise kernels --------------------------------------
__global__ void split_kernel(const float* __restrict__ w,
                             __nv_bfloat16* __restrict__ hi,
                             __nv_bfloat16* __restrict__ lo, int n)
{
    int i = blockIdx.x * blockDim.x + threadIdx.x;
    if (i < n) {
        float v = w[i];
        __nv_bfloat16 h = __float2bfloat16_rn(v);
        hi[i] = h;
        lo[i] = __float2bfloat16_rn(v - __bfloat162float(h));
    }
}

__global__ void gru_combine2(const float* __restrict__ gi0, const float* __restrict__ gh0,
                             float* __restrict__ h0, float* __restrict__ seq0,
                             const float* __restrict__ gi1, const float* __restrict__ gh1,
                             float* __restrict__ h1)
{
    int idx = blockIdx.x * blockDim.x + threadIdx.x;
    const float *gi, *gh; float *h, *so = nullptr;
    if (idx < BB * FS) { gi = gi0; gh = gh0; h = h0; so = seq0; }
    else               { idx -= BB * FS; gi = gi1; gh = gh1; h = h1; }
    int m = idx >> 10, j = idx & (FS - 1);
    size_t base = (size_t)m * G3 + j;
    float ir = gi[base], iz = gi[base + FS], in = gi[base + 2 * FS];
    float hr = gh[base], hz = gh[base + FS], hn = gh[base + 2 * FS];
    float r = 1.0f / (1.0f + expf(-(ir + hr)));
    float z = 1.0f / (1.0f + expf(-(iz + hz)));
    float n = tanhf(in + r * hn);
    float hv = (1.0f - z) * n + z * h[idx];
    h[idx] = hv;
    if (so) so[idx] = hv;
}

__global__ void reward_kernel(const float* __restrict__ h1,
                              const float* __restrict__ Wr,
                              const float* __restrict__ br,
                              float* __restrict__ out_r, int t)
{
    int g = blockIdx.x * blockDim.x + threadIdx.x;
    int warp = g >> 5, lane = g & 31;
    if (warp >= BB) return;
    const float* hr = h1 + (size_t)warp * FS;
    float s = 0.0f;
    #pragma unroll 8
    for (int k = lane; k < FS; k += 32) s += hr[k] * Wr[k];
    #pragma unroll
    for (int o = 16; o; o >>= 1) s += __shfl_xor_sync(0xFFFFFFFFu, s, o);
    if (lane == 0)
        out_r[warp * TFN + t] = 1.0f / (1.0f + expf(-(s + br[0])));
}

__global__ void zero_h(float* __restrict__ a, float* __restrict__ b)
{
    int idx = blockIdx.x * blockDim.x + threadIdx.x;
    if (idx < BB * FS) { a[idx] = 0.0f; b[idx] = 0.0f; }
}

// ---------------- host orchestration ---------------------------------------
static GTask mk(const float* A, int64_t lda, const __nv_bfloat16* Wh, const __nv_bfloat16* Wl,
                const float* bias, float* C, int64_t ldc,
                float* C2 = nullptr, int64_t ldc2 = 0, int act = 0, int rowmap = 0)
{
    GTask t; t.A = A; t.lda = lda; t.Wh = Wh; t.Wl = Wl; t.bias = bias;
    t.C = C; t.ldc = ldc; t.C2 = C2; t.ldc2 = ldc2; t.act = act; t.rowmap = rowmap;
    return t;
}

static void mm1(const GTask& a, int M, int N, int K) {
    dim3 g(N / 128, M / 128, 1);
    mm_kernel<<<g, 256>>>(a, a, a, K);
}
static void mm2(const GTask& a, const GTask& b, int M, int N, int K) {
    dim3 g(N / 128, M / 128, 2);
    mm_kernel<<<g, 256>>>(a, b, a, K);
}
static void mm3(const GTask& a, const GTask& b, const GTask& c, int M, int N, int K) {
    dim3 g(N / 128, M / 128, 3);
    mm_kernel<<<g, 256>>>(a, b, c, K);
}

extern "C" void kernel_launch(void* const* d_in, const int* in_sizes, int n_in,
                              void* d_out, int out_size)
{
    const float* history_s = (const float*)d_in[0];
    const float* history_a = (const float*)d_in[1];
    const float* present_s = (const float*)d_in[2];
    const float* future_a  = (const float*)d_in[3];
    const float* Ws  = (const float*)d_in[4];
    const float* bs  = (const float*)d_in[5];
    const float* Wa  = (const float*)d_in[6];
    const float* ba  = (const float*)d_in[7];
    const float* Wih = (const float*)d_in[8];
    const float* Whh = (const float*)d_in[9];
    const float* bih = (const float*)d_in[10];
    const float* bhh = (const float*)d_in[11];
    const float* Wr  = (const float*)d_in[12];
    const float* br  = (const float*)d_in[13];
    const float* Ws2 = (const float*)d_in[14];
    const float* bs2 = (const float*)d_in[15];

    float* out_r = (float*)d_out;
    float* out_s = (float*)d_out + BB * TFN;

    float *xs, *seq0, *gi, *gh0b, *gh1b, *gi1b, *h0, *h1, *x, *sbuf;
    cudaGetSymbolAddress((void**)&xs,   g_xs);
    cudaGetSymbolAddress((void**)&seq0, g_seq0);
    cudaGetSymbolAddress((void**)&gi,   g_gi);
    cudaGetSymbolAddress((void**)&gh0b, g_gh0);
    cudaGetSymbolAddress((void**)&gh1b, g_gh1);
    cudaGetSymbolAddress((void**)&gi1b, g_gi1);
    cudaGetSymbolAddress((void**)&h0,   g_h0);
    cudaGetSymbolAddress((void**)&h1,   g_h1);
    cudaGetSymbolAddress((void**)&x,    g_x);
    cudaGetSymbolAddress((void**)&sbuf, g_s);

    __nv_bfloat16 *Ws_h, *Ws_l, *Wa_h, *Wa_l, *Wih_h, *Wih_l, *Whh_h, *Whh_l, *Ws2_h, *Ws2_l;
    cudaGetSymbolAddress((void**)&Ws_h,  g_Ws_hi);  cudaGetSymbolAddress((void**)&Ws_l,  g_Ws_lo);
    cudaGetSymbolAddress((void**)&Wa_h,  g_Wa_hi);  cudaGetSymbolAddress((void**)&Wa_l,  g_Wa_lo);
    cudaGetSymbolAddress((void**)&Wih_h, g_Wih_hi); cudaGetSymbolAddress((void**)&Wih_l, g_Wih_lo);
    cudaGetSymbolAddress((void**)&Whh_h, g_Whh_hi); cudaGetSymbolAddress((void**)&Whh_l, g_Whh_lo);
    cudaGetSymbolAddress((void**)&Ws2_h, g_Ws2_hi); cudaGetSymbolAddress((void**)&Ws2_l, g_Ws2_lo);

    auto split = [](const float* w, __nv_bfloat16* hi, __nv_bfloat16* lo, int n) {
        split_kernel<<<(n + 255) / 256, 256>>>(w, hi, lo, n);
    };
    split(Ws,  Ws_h,  Ws_l,  FS * SS);
    split(Wa,  Wa_h,  Wa_l,  FS * AS);
    split(Wih, Wih_h, Wih_l, 2 * G3 * FS);
    split(Whh, Whh_h, Whh_l, 2 * G3 * FS);
    split(Ws2, Ws2_h, Ws2_l, SS * FS);

    const __nv_bfloat16 *Wih0h = Wih_h, *Wih0l = Wih_l;
    const __nv_bfloat16 *Wih1h = Wih_h + (size_t)G3 * FS, *Wih1l = Wih_l + (size_t)G3 * FS;
    const __nv_bfloat16 *Whh0h = Whh_h, *Whh0l = Whh_l;
    const __nv_bfloat16 *Whh1h = Whh_h + (size_t)G3 * FS, *Whh1l = Whh_l + (size_t)G3 * FS;
    const float *bih0 = bih, *bih1 = bih + G3, *bhh0 = bhh, *bhh1 = bhh + G3;

    zero_h<<<(BB * FS + 255) / 256, 256>>>(h0, h1);

    // prefix embeddings into xs [t][b][f]
    mm1(mk(history_s, SS, Ws_h, Ws_l, bs, xs, FS, nullptr, 0, 1, 1), BB * THN, FS, SS);
    mm1(mk(history_a, AS, Wa_h, Wa_l, ba, xs, FS, nullptr, 0, 1, 2), BB * THN, FS, AS);
    mm1(mk(present_s, SS, Ws_h, Ws_l, bs, xs + (size_t)(TT - 1) * BB * FS, FS,
           nullptr, 0, 1, 0), BB, FS, SS);

    // layer-0 input gates for all prefix steps (batched)
    mm1(mk(xs, FS, Wih0h, Wih0l, bih0, gi, G3), TT * BB, G3, FS);

    auto combine1 = [&](const float* a, const float* b, float* h, float* so) {
        gru_combine2<<<(BB * FS) / 256, 256>>>(a, b, h, so, nullptr, nullptr, nullptr);
    };
    auto combine2 = [&](const float* a0, const float* b0, float* hh0, float* so,
                        const float* a1, const float* b1, float* hh1) {
        gru_combine2<<<(2 * BB * FS) / 256, 256>>>(a0, b0, hh0, so, a1, b1, hh1);
    };

    // interleaved two-layer prefix scan (L1 lags one step behind L0)
    mm1(mk(h0, FS, Whh0h, Whh0l, bhh0, gh0b, G3), BB, G3, FS);
    combine1(gi, gh0b, h0, seq0);
    for (int tau = 0; tau < TT - 1; tau++) {
        mm3(mk(h0, FS, Whh0h, Whh0l, bhh0, gh0b, G3),
            mk(seq0 + (size_t)tau * BB * FS, FS, Wih1h, Wih1l, bih1, gi1b, G3),
            mk(h1, FS, Whh1h, Whh1l, bhh1, gh1b, G3),
            BB, G3, FS);
        combine2(gi + (size_t)(tau + 1) * BB * G3, gh0b, h0,
                 seq0 + (size_t)(tau + 1) * BB * FS, gi1b, gh1b, h1);
    }
    mm2(mk(seq0 + (size_t)(TT - 1) * BB * FS, FS, Wih1h, Wih1l, bih1, gi1b, G3),
        mk(h1, FS, Whh1h, Whh1l, bhh1, gh1b, G3), BB, G3, FS);
    combine1(gi1b, gh1b, h1, nullptr);

    // future rollout
    for (int t = 0; t < TFN; t++) {
        mm1(mk(future_a + (size_t)t * AS, (int64_t)TFN * AS, Wa_h, Wa_l, ba, x, FS,
               nullptr, 0, 1, 0), BB, FS, AS);
        mm2(mk(x,  FS, Wih0h, Wih0l, bih0, gi1b, G3),
            mk(h0, FS, Whh0h, Whh0l, bhh0, gh0b, G3), BB, G3, FS);
        combine1(gi1b, gh0b, h0, nullptr);
        mm2(mk(h0, FS, Wih1h, Wih1l, bih1, gi1b, G3),
            mk(h1, FS, Whh1h, Whh1l, bhh1, gh1b, G3), BB, G3, FS);
        combine1(gi1b, gh1b, h1, nullptr);

        reward_kernel<<<(BB * 32 + 255) / 256, 256>>>(h1, Wr, br, out_r, t);
        mm1(mk(h1, FS, Ws2_h, Ws2_l, bs2, sbuf, SS,
               out_s + (size_t)t * SS, (int64_t)TFN * SS, 1, 0), BB, SS, FS);
        mm1(mk(sbuf, SS, Ws_h, Ws_l, bs, x, FS, nullptr, 0, 1, 0), BB, FS, SS);

        mm2(mk(x,  FS, Wih0h, Wih0l, bih0, gi1b, G3),
            mk(h0, FS, Whh0h, Whh0l, bhh0, gh0b, G3), BB, G3, FS);
        combine1(gi1b, gh0b, h0, nullptr);
        mm2(mk(h0, FS, Wih1h, Wih1l, bih1, gi1b, G3),
            mk(h1, FS, Whh1h, Whh1l, bhh1, gh1b, G3), BB, G3, FS);
        combine1(gi1b, gh1b, h1, nullptr);
    }
}

// round 8
// speedup vs baseline: 3.1708x; 1.0047x over previous
#include <cuda_runtime.h>
#include <cuda_bf16.h>
#include <cstdint>
#include <math.h>

constexpr int BB  = 256;
constexpr int THN = 32;
constexpr int TFN = 16;
constexpr int SS  = 512;
constexpr int AS  = 128;
constexpr int FS  = 1024;
constexpr int G3  = 3072;
constexpr int TT  = 65;

// ---------------- scratch (device globals; no allocation allowed) ----------
__device__ float g_gi  [TT * BB * G3];     // prefix layer-0 input gates (fp32)
__device__ float g_gh0 [BB * G3];
__device__ float g_gh1 [BB * G3];
__device__ float g_gi1 [BB * G3];
__device__ float g_h0f [BB * FS];
__device__ float g_h1f [BB * FS];

// bf16 hi/lo planes for all GEMM A-operands
__device__ __nv_bfloat16 g_xs_hi[TT * BB * FS], g_xs_lo[TT * BB * FS];
__device__ __nv_bfloat16 g_h0h[BB * FS], g_h0l[BB * FS];
__device__ __nv_bfloat16 g_h1h[BB * FS], g_h1l[BB * FS];
__device__ __nv_bfloat16 g_xh [BB * FS], g_xl [BB * FS];
__device__ __nv_bfloat16 g_sh [BB * SS], g_sl [BB * SS];
__device__ __nv_bfloat16 g_hs_h[BB * THN * SS], g_hs_l[BB * THN * SS];
__device__ __nv_bfloat16 g_ha_h[BB * THN * AS], g_ha_l[BB * THN * AS];
__device__ __nv_bfloat16 g_ps_h[BB * SS],       g_ps_l[BB * SS];
__device__ __nv_bfloat16 g_fa_h[BB * TFN * AS], g_fa_l[BB * TFN * AS];

// split bf16 weights (hi/lo), laid out [N, K]
__device__ __nv_bfloat16 g_Ws_hi [FS * SS],     g_Ws_lo [FS * SS];
__device__ __nv_bfloat16 g_Wa_hi [FS * AS],     g_Wa_lo [FS * AS];
__device__ __nv_bfloat16 g_Wih_hi[2 * G3 * FS], g_Wih_lo[2 * G3 * FS];
__device__ __nv_bfloat16 g_Whh_hi[2 * G3 * FS], g_Whh_lo[2 * G3 * FS];
__device__ __nv_bfloat16 g_Ws2_hi[SS * FS],     g_Ws2_lo[SS * FS];

// ---------------- PTX helpers ----------------------------------------------
__device__ __forceinline__ uint32_t smem_u32(const void* p) {
    uint32_t a;
    asm("{ .reg .u64 t; cvta.to.shared.u64 t, %1; cvt.u32.u64 %0, t; }"
        : "=r"(a) : "l"(p));
    return a;
}

__device__ __forceinline__ void ldmx4(uint32_t* r, uint32_t addr) {
    asm volatile("ldmatrix.sync.aligned.m8n8.x4.shared.b16 {%0,%1,%2,%3}, [%4];"
                 : "=r"(r[0]), "=r"(r[1]), "=r"(r[2]), "=r"(r[3]) : "r"(addr));
}

__device__ __forceinline__ void mma16816(float* d, const uint32_t* a, const uint32_t* b) {
    asm volatile(
        "mma.sync.aligned.m16n8k16.row.col.f32.bf16.bf16.f32 "
        "{%0,%1,%2,%3}, {%4,%5,%6,%7}, {%8,%9}, {%0,%1,%2,%3};"
        : "+f"(d[0]), "+f"(d[1]), "+f"(d[2]), "+f"(d[3])
        : "r"(a[0]), "r"(a[1]), "r"(a[2]), "r"(a[3]), "r"(b[0]), "r"(b[1]));
}

__device__ __forceinline__ void cpasync16(uint32_t dst, const void* src) {
    asm volatile("cp.async.cg.shared.global [%0], [%1], 16;" :: "r"(dst), "l"(src));
}
#define CP_COMMIT()  asm volatile("cp.async.commit_group;")
#define CP_WAIT1()   asm volatile("cp.async.wait_group 1;")
#define CP_WAIT0()   asm volatile("cp.async.wait_group 0;")

// ---------------- GEMM kernel ----------------------------------------------
// C[m,n] = act( sum_k A[m,k]*W[n,k] + bias[n] )
// A/W as bf16 hi/lo planes; 3-pass split MMA (Ahi*Whi + Ahi*Wlo + Alo*Whi).
// Tile 128x128, BK=64, 2-stage cp.async pipeline, 8 warps (2m x 4n).
struct GTask {
    const __nv_bfloat16 *Ah, *Al; int64_t lda;
    const __nv_bfloat16 *Wh, *Wl;
    const float* bias;
    float* Cf; int64_t ldcf;                 // optional fp32 output
    __nv_bfloat16 *Chi, *Clo; int64_t ldch;  // optional plane output
    int act; int rowmap;
};

constexpr int ST_A_HI = 0;
constexpr int ST_A_LO = 16384;
constexpr int ST_W_HI = 32768;
constexpr int ST_W_LO = 49152;
constexpr int STAGE   = 65536;
constexpr int SMEM_BYTES = 131072;

__device__ __forceinline__ float act_f(float v, int act) {
    if (act == 1) return tanhf(v);
    if (act == 2) return 1.0f / (1.0f + expf(-v));
    return v;
}

__device__ __forceinline__ void issue_stage(
    const GTask& T, int K, int row0, int col0, int k0, uint32_t sbase, int tid)
{
    const int row  = tid >> 1;
    const int colb = (tid & 1) * 64;   // bytes within 128B row
    const int cole = colb >> 1;        // bf16 elements
    const uint32_t dbase  = (uint32_t)(row * 128);
    const uint32_t swmask = (uint32_t)((row & 7) << 4);
    const __nv_bfloat16* a_h = T.Ah + (size_t)(row0 + row) * T.lda + k0 + cole;
    const __nv_bfloat16* a_l = T.Al + (size_t)(row0 + row) * T.lda + k0 + cole;
    const __nv_bfloat16* w_h = T.Wh + (size_t)(col0 + row) * K + k0 + cole;
    const __nv_bfloat16* w_l = T.Wl + (size_t)(col0 + row) * K + k0 + cole;
    #pragma unroll
    for (int j = 0; j < 4; j++) {
        uint32_t sw = (dbase + (uint32_t)(colb + j * 16)) ^ swmask;
        cpasync16(sbase + ST_A_HI + sw, a_h + j * 8);
        cpasync16(sbase + ST_A_LO + sw, a_l + j * 8);
        cpasync16(sbase + ST_W_HI + sw, w_h + j * 8);
        cpasync16(sbase + ST_W_LO + sw, w_l + j * 8);
    }
}

__global__ void __launch_bounds__(256, 1) mm_kernel(GTask T0, GTask T1, GTask T2, int K)
{
    extern __shared__ __align__(16) char sm[];
    const GTask T = (blockIdx.z == 0) ? T0 : (blockIdx.z == 1 ? T1 : T2);
    const uint32_t sb = smem_u32(sm);
    const int tid  = threadIdx.x;
    const int wid  = tid >> 5, lane = tid & 31;
    const int row0 = blockIdx.y * 128, col0 = blockIdx.x * 128;
    const int m0w  = (wid >> 2) * 64;
    const int n0w  = (wid & 3) * 32;

    const int NC = K >> 6;

    issue_stage(T, K, row0, col0, 0, sb, tid);
    CP_COMMIT();
    if (NC > 1) { issue_stage(T, K, row0, col0, 64, sb + STAGE, tid); CP_COMMIT(); }

    float acc[4][4][4];
    #pragma unroll
    for (int i = 0; i < 4; i++)
        #pragma unroll
        for (int j = 0; j < 4; j++)
            #pragma unroll
            for (int q = 0; q < 4; q++) acc[i][j][q] = 0.0f;

    const uint32_t a_lrow  = (uint32_t)(lane & 15);
    const uint32_t a_lcolb = (uint32_t)((lane >> 4) * 16);
    const uint32_t b_lrow  = (uint32_t)((lane & 7) + ((lane >> 4) & 1) * 8);
    const uint32_t b_lcolb = (uint32_t)(((lane >> 3) & 1) * 16);

    for (int c = 0; c < NC; c++) {
        if (c + 1 < NC) { CP_WAIT1(); } else { CP_WAIT0(); }
        __syncthreads();
        const uint32_t st = sb + (uint32_t)((c & 1) * STAGE);

        #pragma unroll
        for (int ks = 0; ks < 4; ks++) {
            const uint32_t kc = (uint32_t)(ks * 32);
            uint32_t Ahi[16], Alo[16], Bhi[8], Blo[8];
            #pragma unroll
            for (int mt = 0; mt < 4; mt++) {
                uint32_t r = (uint32_t)(m0w + mt * 16) + a_lrow;
                uint32_t off = r * 128 + ((kc + a_lcolb) ^ ((r & 7) << 4));
                ldmx4(Ahi + mt * 4, st + ST_A_HI + off);
                ldmx4(Alo + mt * 4, st + ST_A_LO + off);
            }
            #pragma unroll
            for (int p = 0; p < 2; p++) {
                uint32_t r = (uint32_t)(n0w + p * 16) + b_lrow;
                uint32_t off = r * 128 + ((kc + b_lcolb) ^ ((r & 7) << 4));
                ldmx4(Bhi + p * 4, st + ST_W_HI + off);
                ldmx4(Blo + p * 4, st + ST_W_LO + off);
            }
            #pragma unroll
            for (int mt = 0; mt < 4; mt++) {
                #pragma unroll
                for (int nt = 0; nt < 4; nt++) {
                    const uint32_t* bh = &Bhi[(nt >> 1) * 4 + (nt & 1) * 2];
                    const uint32_t* bl = &Blo[(nt >> 1) * 4 + (nt & 1) * 2];
                    mma16816(acc[mt][nt], Ahi + mt * 4, bh);
                    mma16816(acc[mt][nt], Ahi + mt * 4, bl);
                    mma16816(acc[mt][nt], Alo + mt * 4, bh);
                }
            }
        }
        __syncthreads();
        if (c + 2 < NC) {
            issue_stage(T, K, row0, col0, (c + 2) << 6, sb + (uint32_t)((c & 1) * STAGE), tid);
            CP_COMMIT();
        }
    }

    // ---- epilogue: bias + act + rowmap; fp32 and/or plane outputs ----
    const int tq = lane >> 2, tr = lane & 3;
    #pragma unroll
    for (int mt = 0; mt < 4; mt++) {
        #pragma unroll
        for (int half = 0; half < 2; half++) {
            int m = row0 + m0w + mt * 16 + half * 8 + tq;
            int mp;
            if (T.rowmap == 1)      mp = ((m & 31) << 1) * BB + (m >> 5);
            else if (T.rowmap == 2) mp = (((m & 31) << 1) + 1) * BB + (m >> 5);
            else                    mp = m;
            float* cf = T.Cf ? T.Cf + (size_t)mp * T.ldcf : nullptr;
            __nv_bfloat16* chi = T.Chi ? T.Chi + (size_t)mp * T.ldch : nullptr;
            __nv_bfloat16* clo = T.Clo ? T.Clo + (size_t)mp * T.ldch : nullptr;
            #pragma unroll
            for (int nt = 0; nt < 4; nt++) {
                int n = col0 + n0w + nt * 8 + tr * 2;
                float2 bv = *(const float2*)(T.bias + n);
                float vx = act_f(acc[mt][nt][half * 2 + 0] + bv.x, T.act);
                float vy = act_f(acc[mt][nt][half * 2 + 1] + bv.y, T.act);
                if (cf) { float2 o; o.x = vx; o.y = vy; *(float2*)(cf + n) = o; }
                if (chi) {
                    __nv_bfloat16 hx = __float2bfloat16_rn(vx);
                    __nv_bfloat16 hy = __float2bfloat16_rn(vy);
                    float lx = vx - __bfloat162float(hx);
                    float ly = vy - __bfloat162float(hy);
                    uint32_t hp = (uint32_t)__bfloat16_as_ushort(hx)
                                | ((uint32_t)__bfloat16_as_ushort(hy) << 16);
                    uint32_t lp = (uint32_t)__bfloat16_as_ushort(__float2bfloat16_rn(lx))
                                | ((uint32_t)__bfloat16_as_ushort(__float2bfloat16_rn(ly)) << 16);
                    *(uint32_t*)(chi + n) = hp;
                    *(uint32_t*)(clo + n) = lp;
                }
            }
        }
    }
}

// ---------------- elementwise kernels --------------------------------------
__global__ void split_kernel(const float* __restrict__ w,
                             __nv_bfloat16* __restrict__ hi,
                             __nv_bfloat16* __restrict__ lo, int n)
{
    int i = blockIdx.x * blockDim.x + threadIdx.x;
    if (i < n) {
        float v = w[i];
        __nv_bfloat16 h = __float2bfloat16_rn(v);
        hi[i] = h;
        lo[i] = __float2bfloat16_rn(v - __bfloat162float(h));
    }
}

// GRU combine over element pairs; set0 always active, set1 optional (2nd half)
__global__ void gru_combine2(
    const float* __restrict__ gi0, const float* __restrict__ gh0,
    float* __restrict__ h0f, __nv_bfloat16* __restrict__ h0h, __nv_bfloat16* __restrict__ h0l,
    const float* __restrict__ gi1, const float* __restrict__ gh1,
    float* __restrict__ h1f, __nv_bfloat16* __restrict__ h1h, __nv_bfloat16* __restrict__ h1l)
{
    int p = blockIdx.x * blockDim.x + threadIdx.x;
    const float *gi, *gh; float* hf; __nv_bfloat16 *hh, *hl;
    constexpr int NP = BB * FS / 2;
    if (p < NP) { gi = gi0; gh = gh0; hf = h0f; hh = h0h; hl = h0l; }
    else        { p -= NP; gi = gi1; gh = gh1; hf = h1f; hh = h1h; hl = h1l; }
    int m = p >> 9;                 // FS/2 = 512 pairs per row
    int j = (p & 511) * 2;
    size_t base = (size_t)m * G3 + j;
    float2 ir = *(const float2*)(gi + base);
    float2 iz = *(const float2*)(gi + base + FS);
    float2 in = *(const float2*)(gi + base + 2 * FS);
    float2 hr = *(const float2*)(gh + base);
    float2 hz = *(const float2*)(gh + base + FS);
    float2 hn = *(const float2*)(gh + base + 2 * FS);
    int hidx = m * FS + j;
    float2 hold = *(const float2*)(hf + hidx);

    float r0 = 1.0f / (1.0f + expf(-(ir.x + hr.x)));
    float z0 = 1.0f / (1.0f + expf(-(iz.x + hz.x)));
    float n0 = tanhf(in.x + r0 * hn.x);
    float v0 = (1.0f - z0) * n0 + z0 * hold.x;
    float r1 = 1.0f / (1.0f + expf(-(ir.y + hr.y)));
    float z1 = 1.0f / (1.0f + expf(-(iz.y + hz.y)));
    float n1 = tanhf(in.y + r1 * hn.y);
    float v1 = (1.0f - z1) * n1 + z1 * hold.y;

    float2 o; o.x = v0; o.y = v1;
    *(float2*)(hf + hidx) = o;
    __nv_bfloat16 hx = __float2bfloat16_rn(v0);
    __nv_bfloat16 hy = __float2bfloat16_rn(v1);
    uint32_t hp = (uint32_t)__bfloat16_as_ushort(hx)
                | ((uint32_t)__bfloat16_as_ushort(hy) << 16);
    uint32_t lp = (uint32_t)__bfloat16_as_ushort(__float2bfloat16_rn(v0 - __bfloat162float(hx)))
                | ((uint32_t)__bfloat16_as_ushort(__float2bfloat16_rn(v1 - __bfloat162float(hy))) << 16);
    *(uint32_t*)(hh + hidx) = hp;
    *(uint32_t*)(hl + hidx) = lp;
}

__global__ void reward_kernel(const float* __restrict__ h1,
                              const float* __restrict__ Wr,
                              const float* __restrict__ br,
                              float* __restrict__ out_r, int t)
{
    int g = blockIdx.x * blockDim.x + threadIdx.x;
    int warp = g >> 5, lane = g & 31;
    if (warp >= BB) return;
    const float* hr = h1 + (size_t)warp * FS;
    float s = 0.0f;
    #pragma unroll 8
    for (int k = lane; k < FS; k += 32) s += hr[k] * Wr[k];
    #pragma unroll
    for (int o = 16; o; o >>= 1) s += __shfl_xor_sync(0xFFFFFFFFu, s, o);
    if (lane == 0)
        out_r[warp * TFN + t] = 1.0f / (1.0f + expf(-(s + br[0])));
}

__global__ void zero_h(float* __restrict__ a, float* __restrict__ b,
                       __nv_bfloat16* __restrict__ ah, __nv_bfloat16* __restrict__ al,
                       __nv_bfloat16* __restrict__ bh, __nv_bfloat16* __restrict__ bl)
{
    int idx = blockIdx.x * blockDim.x + threadIdx.x;
    if (idx < BB * FS) {
        a[idx] = 0.0f; b[idx] = 0.0f;
        ah[idx] = __float2bfloat16(0.0f); al[idx] = __float2bfloat16(0.0f);
        bh[idx] = __float2bfloat16(0.0f); bl[idx] = __float2bfloat16(0.0f);
    }
}

// ---------------- host orchestration ---------------------------------------
static GTask mk(const __nv_bfloat16* Ah, const __nv_bfloat16* Al, int64_t lda,
                const __nv_bfloat16* Wh, const __nv_bfloat16* Wl, const float* bias,
                float* Cf, int64_t ldcf,
                __nv_bfloat16* Chi, __nv_bfloat16* Clo, int64_t ldch,
                int act, int rowmap)
{
    GTask t; t.Ah = Ah; t.Al = Al; t.lda = lda; t.Wh = Wh; t.Wl = Wl; t.bias = bias;
    t.Cf = Cf; t.ldcf = ldcf; t.Chi = Chi; t.Clo = Clo; t.ldch = ldch;
    t.act = act; t.rowmap = rowmap;
    return t;
}

static void mm1(const GTask& a, int M, int N, int K) {
    dim3 g(N / 128, M / 128, 1);
    mm_kernel<<<g, 256, SMEM_BYTES>>>(a, a, a, K);
}
static void mm2(const GTask& a, const GTask& b, int M, int N, int K) {
    dim3 g(N / 128, M / 128, 2);
    mm_kernel<<<g, 256, SMEM_BYTES>>>(a, b, a, K);
}
static void mm3(const GTask& a, const GTask& b, const GTask& c, int M, int N, int K) {
    dim3 g(N / 128, M / 128, 3);
    mm_kernel<<<g, 256, SMEM_BYTES>>>(a, b, c, K);
}

extern "C" void kernel_launch(void* const* d_in, const int* in_sizes, int n_in,
                              void* d_out, int out_size)
{
    const float* history_s = (const float*)d_in[0];
    const float* history_a = (const float*)d_in[1];
    const float* present_s = (const float*)d_in[2];
    const float* future_a  = (const float*)d_in[3];
    const float* Ws  = (const float*)d_in[4];
    const float* bs  = (const float*)d_in[5];
    const float* Wa  = (const float*)d_in[6];
    const float* ba  = (const float*)d_in[7];
    const float* Wih = (const float*)d_in[8];
    const float* Whh = (const float*)d_in[9];
    const float* bih = (const float*)d_in[10];
    const float* bhh = (const float*)d_in[11];
    const float* Wr  = (const float*)d_in[12];
    const float* br  = (const float*)d_in[13];
    const float* Ws2 = (const float*)d_in[14];
    const float* bs2 = (const float*)d_in[15];

    float* out_r = (float*)d_out;
    float* out_s = (float*)d_out + BB * TFN;

    cudaFuncSetAttribute(mm_kernel, cudaFuncAttributeMaxDynamicSharedMemorySize, SMEM_BYTES);

    float *gi, *gh0b, *gh1b, *gi1b, *h0f, *h1f;
    cudaGetSymbolAddress((void**)&gi,   g_gi);
    cudaGetSymbolAddress((void**)&gh0b, g_gh0);
    cudaGetSymbolAddress((void**)&gh1b, g_gh1);
    cudaGetSymbolAddress((void**)&gi1b, g_gi1);
    cudaGetSymbolAddress((void**)&h0f,  g_h0f);
    cudaGetSymbolAddress((void**)&h1f,  g_h1f);

    __nv_bfloat16 *xs_h, *xs_l, *h0h, *h0l, *h1h, *h1l, *xh, *xl, *sh, *sl;
    __nv_bfloat16 *hs_h, *hs_l, *ha_h, *ha_l, *ps_h, *ps_l, *fa_h, *fa_l;
    cudaGetSymbolAddress((void**)&xs_h, g_xs_hi); cudaGetSymbolAddress((void**)&xs_l, g_xs_lo);
    cudaGetSymbolAddress((void**)&h0h, g_h0h); cudaGetSymbolAddress((void**)&h0l, g_h0l);
    cudaGetSymbolAddress((void**)&h1h, g_h1h); cudaGetSymbolAddress((void**)&h1l, g_h1l);
    cudaGetSymbolAddress((void**)&xh,  g_xh);  cudaGetSymbolAddress((void**)&xl,  g_xl);
    cudaGetSymbolAddress((void**)&sh,  g_sh);  cudaGetSymbolAddress((void**)&sl,  g_sl);
    cudaGetSymbolAddress((void**)&hs_h, g_hs_h); cudaGetSymbolAddress((void**)&hs_l, g_hs_l);
    cudaGetSymbolAddress((void**)&ha_h, g_ha_h); cudaGetSymbolAddress((void**)&ha_l, g_ha_l);
    cudaGetSymbolAddress((void**)&ps_h, g_ps_h); cudaGetSymbolAddress((void**)&ps_l, g_ps_l);
    cudaGetSymbolAddress((void**)&fa_h, g_fa_h); cudaGetSymbolAddress((void**)&fa_l, g_fa_l);

    __nv_bfloat16 *Ws_h, *Ws_l, *Wa_h, *Wa_l, *Wih_h, *Wih_l, *Whh_h, *Whh_l, *Ws2_h, *Ws2_l;
    cudaGetSymbolAddress((void**)&Ws_h,  g_Ws_hi);  cudaGetSymbolAddress((void**)&Ws_l,  g_Ws_lo);
    cudaGetSymbolAddress((void**)&Wa_h,  g_Wa_hi);  cudaGetSymbolAddress((void**)&Wa_l,  g_Wa_lo);
    cudaGetSymbolAddress((void**)&Wih_h, g_Wih_hi); cudaGetSymbolAddress((void**)&Wih_l, g_Wih_lo);
    cudaGetSymbolAddress((void**)&Whh_h, g_Whh_hi); cudaGetSymbolAddress((void**)&Whh_l, g_Whh_lo);
    cudaGetSymbolAddress((void**)&Ws2_h, g_Ws2_hi); cudaGetSymbolAddress((void**)&Ws2_l, g_Ws2_lo);

    auto split = [](const float* w, __nv_bfloat16* hi, __nv_bfloat16* lo, int n) {
        split_kernel<<<(n + 255) / 256, 256>>>(w, hi, lo, n);
    };
    split(Ws,  Ws_h,  Ws_l,  FS * SS);
    split(Wa,  Wa_h,  Wa_l,  FS * AS);
    split(Wih, Wih_h, Wih_l, 2 * G3 * FS);
    split(Whh, Whh_h, Whh_l, 2 * G3 * FS);
    split(Ws2, Ws2_h, Ws2_l, SS * FS);
    split(history_s, hs_h, hs_l, BB * THN * SS);
    split(history_a, ha_h, ha_l, BB * THN * AS);
    split(present_s, ps_h, ps_l, BB * SS);
    split(future_a,  fa_h, fa_l, BB * TFN * AS);

    const __nv_bfloat16 *Wih0h = Wih_h, *Wih0l = Wih_l;
    const __nv_bfloat16 *Wih1h = Wih_h + (size_t)G3 * FS, *Wih1l = Wih_l + (size_t)G3 * FS;
    const __nv_bfloat16 *Whh0h = Whh_h, *Whh0l = Whh_l;
    const __nv_bfloat16 *Whh1h = Whh_h + (size_t)G3 * FS, *Whh1l = Whh_l + (size_t)G3 * FS;
    const float *bih0 = bih, *bih1 = bih + G3, *bhh0 = bhh, *bhh1 = bhh + G3;

    zero_h<<<(BB * FS + 255) / 256, 256>>>(h0f, h1f, h0h, h0l, h1h, h1l);

    // prefix embeddings -> xs planes [t][b][f] (interleaved; present last)
    mm1(mk(hs_h, hs_l, SS, Ws_h, Ws_l, bs, nullptr, 0, xs_h, xs_l, FS, 1, 1),
        BB * THN, FS, SS);
    mm1(mk(ha_h, ha_l, AS, Wa_h, Wa_l, ba, nullptr, 0, xs_h, xs_l, FS, 1, 2),
        BB * THN, FS, AS);
    mm1(mk(ps_h, ps_l, SS, Ws_h, Ws_l, bs, nullptr, 0,
           xs_h + (size_t)(TT - 1) * BB * FS, xs_l + (size_t)(TT - 1) * BB * FS, FS, 1, 0),
        BB, FS, SS);

    // layer-0 input gates for all prefix steps (batched)
    mm1(mk(xs_h, xs_l, FS, Wih0h, Wih0l, bih0, gi, G3, nullptr, nullptr, 0, 0, 0),
        TT * BB, G3, FS);

    auto combine1 = [&](const float* a, const float* b,
                        float* hf, __nv_bfloat16* hh, __nv_bfloat16* hl) {
        gru_combine2<<<(BB * FS / 2) / 256, 256>>>(a, b, hf, hh, hl,
                                                   nullptr, nullptr, nullptr, nullptr, nullptr);
    };
    auto combine2 = [&](const float* a0, const float* b0) {
        gru_combine2<<<(BB * FS) / 256, 256>>>(a0, b0, h0f, h0h, h0l,
                                               gi1b, gh1b, h1f, h1h, h1l);
    };

    // interleaved two-layer prefix scan (L1 lags one step behind L0)
    mm1(mk(h0h, h0l, FS, Whh0h, Whh0l, bhh0, gh0b, G3, nullptr, nullptr, 0, 0, 0),
        BB, G3, FS);
    combine1(gi, gh0b, h0f, h0h, h0l);
    for (int tau = 0; tau < TT - 1; tau++) {
        mm3(mk(h0h, h0l, FS, Whh0h, Whh0l, bhh0, gh0b, G3, nullptr, nullptr, 0, 0, 0),
            mk(h0h, h0l, FS, Wih1h, Wih1l, bih1, gi1b, G3, nullptr, nullptr, 0, 0, 0),
            mk(h1h, h1l, FS, Whh1h, Whh1l, bhh1, gh1b, G3, nullptr, nullptr, 0, 0, 0),
            BB, G3, FS);
        combine2(gi + (size_t)(tau + 1) * BB * G3, gh0b);
    }
    mm2(mk(h0h, h0l, FS, Wih1h, Wih1l, bih1, gi1b, G3, nullptr, nullptr, 0, 0, 0),
        mk(h1h, h1l, FS, Whh1h, Whh1l, bhh1, gh1b, G3, nullptr, nullptr, 0, 0, 0),
        BB, G3, FS);
    combine1(gi1b, gh1b, h1f, h1h, h1l);

    // future rollout
    for (int t = 0; t < TFN; t++) {
        mm1(mk(fa_h + (size_t)t * AS, fa_l + (size_t)t * AS, (int64_t)TFN * AS,
               Wa_h, Wa_l, ba, nullptr, 0, xh, xl, FS, 1, 0), BB, FS, AS);
        mm2(mk(xh,  xl,  FS, Wih0h, Wih0l, bih0, gi1b, G3, nullptr, nullptr, 0, 0, 0),
            mk(h0h, h0l, FS, Whh0h, Whh0l, bhh0, gh0b, G3, nullptr, nullptr, 0, 0, 0),
            BB, G3, FS);
        combine1(gi1b, gh0b, h0f, h0h, h0l);
        mm2(mk(h0h, h0l, FS, Wih1h, Wih1l, bih1, gi1b, G3, nullptr, nullptr, 0, 0, 0),
            mk(h1h, h1l, FS, Whh1h, Whh1l, bhh1, gh1b, G3, nullptr, nullptr, 0, 0, 0),
            BB, G3, FS);
        combine1(gi1b, gh1b, h1f, h1h, h1l);

        reward_kernel<<<(BB * 32 + 255) / 256, 256>>>(h1f, Wr, br, out_r, t);
        mm1(mk(h1h, h1l, FS, Ws2_h, Ws2_l, bs2,
               out_s + (size_t)t * SS, (int64_t)TFN * SS, sh, sl, SS, 1, 0),
            BB, SS, FS);
        mm1(mk(sh, sl, SS, Ws_h, Ws_l, bs, nullptr, 0, xh, xl, FS, 1, 0), BB, FS, SS);

        mm2(mk(xh,  xl,  FS, Wih0h, Wih0l, bih0, gi1b, G3, nullptr, nullptr, 0, 0, 0),
            mk(h0h, h0l, FS, Whh0h, Whh0l, bhh0, gh0b, G3, nullptr, nullptr, 0, 0, 0),
            BB, G3, FS);
        combine1(gi1b, gh0b, h0f, h0h, h0l);
        mm2(mk(h0h, h0l, FS, Wih1h, Wih1l, bih1, gi1b, G3, nullptr, nullptr, 0, 0, 0),
            mk(h1h, h1l, FS, Whh1h, Whh1l, bhh1, gh1b, G3, nullptr, nullptr, 0, 0, 0),
            BB, G3, FS);
        combine1(gi1b, gh1b, h1f, h1h, h1l);
    }
}

// round 13
// speedup vs baseline: 4.0542x; 1.2786x over previous
#include <cuda_runtime.h>
#include <cuda_fp16.h>
#include <cstdint>
#include <math.h>

constexpr int BB  = 256;
constexpr int THN = 32;
constexpr int TFN = 16;
constexpr int SS  = 512;
constexpr int AS  = 128;
constexpr int FS  = 1024;
constexpr int G3  = 3072;
constexpr int TT  = 65;

// ---------------- scratch (device globals; no allocation allowed) ----------
__device__ float g_gi  [TT * BB * G3];     // prefix layer-0 input gates (fp32)
__device__ float g_gh0 [BB * G3];
__device__ float g_gh1 [BB * G3];
__device__ float g_gi1 [BB * G3];
__device__ float g_h0f [BB * FS];
__device__ float g_h1f [BB * FS];

// fp16 activation planes (single, hi only)
__device__ __half g_xs_h[TT * BB * FS];
__device__ __half g_h0h[BB * FS];
__device__ __half g_h1h[BB * FS];
__device__ __half g_xh [BB * FS];
__device__ __half g_sh [BB * SS];
__device__ __half g_hs [BB * THN * SS];
__device__ __half g_ha [BB * THN * AS];
__device__ __half g_ps [BB * SS];
__device__ __half g_fa [BB * TFN * AS];

// split fp16 weights (hi/lo), laid out [N, K]
__device__ __half g_Ws_hi [FS * SS],     g_Ws_lo [FS * SS];
__device__ __half g_Wa_hi [FS * AS],     g_Wa_lo [FS * AS];
__device__ __half g_Wih_hi[2 * G3 * FS], g_Wih_lo[2 * G3 * FS];
__device__ __half g_Whh_hi[2 * G3 * FS], g_Whh_lo[2 * G3 * FS];
__device__ __half g_Ws2_hi[SS * FS],     g_Ws2_lo[SS * FS];

// ---------------- PTX helpers ----------------------------------------------
__device__ __forceinline__ uint32_t smem_u32(const void* p) {
    uint32_t a;
    asm("{ .reg .u64 t; cvta.to.shared.u64 t, %1; cvt.u32.u64 %0, t; }"
        : "=r"(a) : "l"(p));
    return a;
}

__device__ __forceinline__ void ldmx4(uint32_t* r, uint32_t addr) {
    asm volatile("ldmatrix.sync.aligned.m8n8.x4.shared.b16 {%0,%1,%2,%3}, [%4];"
                 : "=r"(r[0]), "=r"(r[1]), "=r"(r[2]), "=r"(r[3]) : "r"(addr));
}

__device__ __forceinline__ void mma16816(float* d, const uint32_t* a, const uint32_t* b) {
    asm volatile(
        "mma.sync.aligned.m16n8k16.row.col.f32.f16.f16.f32 "
        "{%0,%1,%2,%3}, {%4,%5,%6,%7}, {%8,%9}, {%0,%1,%2,%3};"
        : "+f"(d[0]), "+f"(d[1]), "+f"(d[2]), "+f"(d[3])
        : "r"(a[0]), "r"(a[1]), "r"(a[2]), "r"(a[3]), "r"(b[0]), "r"(b[1]));
}

__device__ __forceinline__ void cpasync16(uint32_t dst, const void* src) {
    asm volatile("cp.async.cg.shared.global [%0], [%1], 16;" :: "r"(dst), "l"(src));
}
#define CP_COMMIT()  asm volatile("cp.async.commit_group;")
#define CP_WAIT1()   asm volatile("cp.async.wait_group 1;")
#define CP_WAIT0()   asm volatile("cp.async.wait_group 0;")

// ---------------- GEMM kernel ----------------------------------------------
// C[m,n] = act( sum_k A[m,k]*W[n,k] + bias[n] )
// A single fp16 plane; W fp16 hi/lo. 2-pass MMA: A*Wh + A*Wl, fp32 accumulate.
// Tile 128x128, BK=64, 2-stage cp.async pipeline, 8 warps (2m x 4n).
struct GTask {
    const __half* A; int64_t lda;
    const __half *Wh, *Wl;
    const float* bias;
    float* Cf; int64_t ldcf;           // optional fp32 output
    __half* Ch; int64_t ldch;          // optional fp16 plane output
    int act; int rowmap;
};

constexpr int ST_A  = 0;
constexpr int ST_WH = 16384;
constexpr int ST_WL = 32768;
constexpr int STAGE = 49152;
constexpr int SMEM_BYTES = 98304;

__device__ __forceinline__ float act_f(float v, int act) {
    if (act == 1) return tanhf(v);
    if (act == 2) return 1.0f / (1.0f + expf(-v));
    return v;
}

__device__ __forceinline__ void issue_stage(
    const GTask& T, int K, int row0, int col0, int k0, uint32_t sbase, int tid)
{
    const int row  = tid >> 1;
    const int colb = (tid & 1) * 64;   // bytes within 128B row
    const int cole = colb >> 1;        // fp16 elements
    const uint32_t dbase  = (uint32_t)(row * 128);
    const uint32_t swmask = (uint32_t)((row & 7) << 4);
    const __half* a_p = T.A  + (size_t)(row0 + row) * T.lda + k0 + cole;
    const __half* w_h = T.Wh + (size_t)(col0 + row) * K + k0 + cole;
    const __half* w_l = T.Wl + (size_t)(col0 + row) * K + k0 + cole;
    #pragma unroll
    for (int j = 0; j < 4; j++) {
        uint32_t sw = (dbase + (uint32_t)(colb + j * 16)) ^ swmask;
        cpasync16(sbase + ST_A  + sw, a_p + j * 8);
        cpasync16(sbase + ST_WH + sw, w_h + j * 8);
        cpasync16(sbase + ST_WL + sw, w_l + j * 8);
    }
}

__global__ void __launch_bounds__(256, 1) mm_kernel(GTask T0, GTask T1, GTask T2, int K)
{
    extern __shared__ __align__(16) char sm[];
    const GTask T = (blockIdx.z == 0) ? T0 : (blockIdx.z == 1 ? T1 : T2);
    const uint32_t sb = smem_u32(sm);
    const int tid  = threadIdx.x;
    const int wid  = tid >> 5, lane = tid & 31;
    const int row0 = blockIdx.y * 128, col0 = blockIdx.x * 128;
    const int m0w  = (wid >> 2) * 64;
    const int n0w  = (wid & 3) * 32;

    const int NC = K >> 6;

    issue_stage(T, K, row0, col0, 0, sb, tid);
    CP_COMMIT();
    if (NC > 1) { issue_stage(T, K, row0, col0, 64, sb + STAGE, tid); CP_COMMIT(); }

    float acc[4][4][4];
    #pragma unroll
    for (int i = 0; i < 4; i++)
        #pragma unroll
        for (int j = 0; j < 4; j++)
            #pragma unroll
            for (int q = 0; q < 4; q++) acc[i][j][q] = 0.0f;

    const uint32_t a_lrow  = (uint32_t)(lane & 15);
    const uint32_t a_lcolb = (uint32_t)((lane >> 4) * 16);
    const uint32_t b_lrow  = (uint32_t)((lane & 7) + ((lane >> 4) & 1) * 8);
    const uint32_t b_lcolb = (uint32_t)(((lane >> 3) & 1) * 16);

    for (int c = 0; c < NC; c++) {
        if (c + 1 < NC) { CP_WAIT1(); } else { CP_WAIT0(); }
        __syncthreads();
        const uint32_t st = sb + (uint32_t)((c & 1) * STAGE);

        #pragma unroll
        for (int ks = 0; ks < 4; ks++) {
            const uint32_t kc = (uint32_t)(ks * 32);
            uint32_t Af[16], Bh[8], Bl[8];
            #pragma unroll
            for (int mt = 0; mt < 4; mt++) {
                uint32_t r = (uint32_t)(m0w + mt * 16) + a_lrow;
                uint32_t off = r * 128 + ((kc + a_lcolb) ^ ((r & 7) << 4));
                ldmx4(Af + mt * 4, st + ST_A + off);
            }
            #pragma unroll
            for (int p = 0; p < 2; p++) {
                uint32_t r = (uint32_t)(n0w + p * 16) + b_lrow;
                uint32_t off = r * 128 + ((kc + b_lcolb) ^ ((r & 7) << 4));
                ldmx4(Bh + p * 4, st + ST_WH + off);
                ldmx4(Bl + p * 4, st + ST_WL + off);
            }
            #pragma unroll
            for (int mt = 0; mt < 4; mt++) {
                #pragma unroll
                for (int nt = 0; nt < 4; nt++) {
                    const uint32_t* bh = &Bh[(nt >> 1) * 4 + (nt & 1) * 2];
                    const uint32_t* bl = &Bl[(nt >> 1) * 4 + (nt & 1) * 2];
                    mma16816(acc[mt][nt], Af + mt * 4, bh);
                    mma16816(acc[mt][nt], Af + mt * 4, bl);
                }
            }
        }
        __syncthreads();
        if (c + 2 < NC) {
            issue_stage(T, K, row0, col0, (c + 2) << 6, sb + (uint32_t)((c & 1) * STAGE), tid);
            CP_COMMIT();
        }
    }

    // ---- epilogue: bias + act + rowmap; fp32 and/or fp16-plane outputs ----
    const int tq = lane >> 2, tr = lane & 3;
    #pragma unroll
    for (int mt = 0; mt < 4; mt++) {
        #pragma unroll
        for (int half = 0; half < 2; half++) {
            int m = row0 + m0w + mt * 16 + half * 8 + tq;
            int mp;
            if (T.rowmap == 1)      mp = ((m & 31) << 1) * BB + (m >> 5);
            else if (T.rowmap == 2) mp = (((m & 31) << 1) + 1) * BB + (m >> 5);
            else                    mp = m;
            float* cf = T.Cf ? T.Cf + (size_t)mp * T.ldcf : nullptr;
            __half* ch = T.Ch ? T.Ch + (size_t)mp * T.ldch : nullptr;
            #pragma unroll
            for (int nt = 0; nt < 4; nt++) {
                int n = col0 + n0w + nt * 8 + tr * 2;
                float2 bv = *(const float2*)(T.bias + n);
                float vx = act_f(acc[mt][nt][half * 2 + 0] + bv.x, T.act);
                float vy = act_f(acc[mt][nt][half * 2 + 1] + bv.y, T.act);
                if (cf) { float2 o; o.x = vx; o.y = vy; *(float2*)(cf + n) = o; }
                if (ch) {
                    uint32_t hp = (uint32_t)__half_as_ushort(__float2half_rn(vx))
                                | ((uint32_t)__half_as_ushort(__float2half_rn(vy)) << 16);
                    *(uint32_t*)(ch + n) = hp;
                }
            }
        }
    }
}

// ---------------- elementwise kernels --------------------------------------
__global__ void split_w_kernel(const float* __restrict__ w,
                               __half* __restrict__ hi,
                               __half* __restrict__ lo, int n)
{
    int i = blockIdx.x * blockDim.x + threadIdx.x;
    if (i < n) {
        float v = w[i];
        __half h = __float2half_rn(v);
        hi[i] = h;
        lo[i] = __float2half_rn(v - __half2float(h));
    }
}

__global__ void tohalf_kernel(const float* __restrict__ w,
                              __half* __restrict__ o, int n)
{
    int i = blockIdx.x * blockDim.x + threadIdx.x;
    if (i < n) o[i] = __float2half_rn(w[i]);
}

// GRU combine over element pairs; set0 always active, set1 optional (2nd half)
__global__ void gru_combine2(
    const float* __restrict__ gi0, const float* __restrict__ gh0,
    float* __restrict__ h0f, __half* __restrict__ h0h,
    const float* __restrict__ gi1, const float* __restrict__ gh1,
    float* __restrict__ h1f, __half* __restrict__ h1h)
{
    int p = blockIdx.x * blockDim.x + threadIdx.x;
    const float *gi, *gh; float* hf; __half* hh;
    constexpr int NP = BB * FS / 2;
    if (p < NP) { gi = gi0; gh = gh0; hf = h0f; hh = h0h; }
    else        { p -= NP; gi = gi1; gh = gh1; hf = h1f; hh = h1h; }
    int m = p >> 9;                 // FS/2 = 512 pairs per row
    int j = (p & 511) * 2;
    size_t base = (size_t)m * G3 + j;
    float2 ir = *(const float2*)(gi + base);
    float2 iz = *(const float2*)(gi + base + FS);
    float2 in = *(const float2*)(gi + base + 2 * FS);
    float2 hr = *(const float2*)(gh + base);
    float2 hz = *(const float2*)(gh + base + FS);
    float2 hn = *(const float2*)(gh + base + 2 * FS);
    int hidx = m * FS + j;
    float2 hold = *(const float2*)(hf + hidx);

    float r0 = 1.0f / (1.0f + expf(-(ir.x + hr.x)));
    float z0 = 1.0f / (1.0f + expf(-(iz.x + hz.x)));
    float n0 = tanhf(in.x + r0 * hn.x);
    float v0 = (1.0f - z0) * n0 + z0 * hold.x;
    float r1 = 1.0f / (1.0f + expf(-(ir.y + hr.y)));
    float z1 = 1.0f / (1.0f + expf(-(iz.y + hz.y)));
    float n1 = tanhf(in.y + r1 * hn.y);
    float v1 = (1.0f - z1) * n1 + z1 * hold.y;

    float2 o; o.x = v0; o.y = v1;
    *(float2*)(hf + hidx) = o;
    uint32_t hp = (uint32_t)__half_as_ushort(__float2half_rn(v0))
                | ((uint32_t)__half_as_ushort(__float2half_rn(v1)) << 16);
    *(uint32_t*)(hh + hidx) = hp;
}

__global__ void reward_kernel(const float* __restrict__ h1,
                              const float* __restrict__ Wr,
                              const float* __restrict__ br,
                              float* __restrict__ out_r, int t)
{
    int g = blockIdx.x * blockDim.x + threadIdx.x;
    int warp = g >> 5, lane = g & 31;
    if (warp >= BB) return;
    const float* hr = h1 + (size_t)warp * FS;
    float s = 0.0f;
    #pragma unroll 8
    for (int k = lane; k < FS; k += 32) s += hr[k] * Wr[k];
    #pragma unroll
    for (int o = 16; o; o >>= 1) s += __shfl_xor_sync(0xFFFFFFFFu, s, o);
    if (lane == 0)
        out_r[warp * TFN + t] = 1.0f / (1.0f + expf(-(s + br[0])));
}

__global__ void zero_h(float* __restrict__ a, float* __restrict__ b,
                       __half* __restrict__ ah, __half* __restrict__ bh)
{
    int idx = blockIdx.x * blockDim.x + threadIdx.x;
    if (idx < BB * FS) {
        a[idx] = 0.0f; b[idx] = 0.0f;
        ah[idx] = __float2half(0.0f); bh[idx] = __float2half(0.0f);
    }
}

// ---------------- host orchestration ---------------------------------------
static GTask mk(const __half* A, int64_t lda,
                const __half* Wh, const __half* Wl, const float* bias,
                float* Cf, int64_t ldcf, __half* Ch, int64_t ldch,
                int act, int rowmap)
{
    GTask t; t.A = A; t.lda = lda; t.Wh = Wh; t.Wl = Wl; t.bias = bias;
    t.Cf = Cf; t.ldcf = ldcf; t.Ch = Ch; t.ldch = ldch;
    t.act = act; t.rowmap = rowmap;
    return t;
}

static void mm1(const GTask& a, int M, int N, int K) {
    dim3 g(N / 128, M / 128, 1);
    mm_kernel<<<g, 256, SMEM_BYTES>>>(a, a, a, K);
}
static void mm2(const GTask& a, const GTask& b, int M, int N, int K) {
    dim3 g(N / 128, M / 128, 2);
    mm_kernel<<<g, 256, SMEM_BYTES>>>(a, b, a, K);
}
static void mm3(const GTask& a, const GTask& b, const GTask& c, int M, int N, int K) {
    dim3 g(N / 128, M / 128, 3);
    mm_kernel<<<g, 256, SMEM_BYTES>>>(a, b, c, K);
}

extern "C" void kernel_launch(void* const* d_in, const int* in_sizes, int n_in,
                              void* d_out, int out_size)
{
    const float* history_s = (const float*)d_in[0];
    const float* history_a = (const float*)d_in[1];
    const float* present_s = (const float*)d_in[2];
    const float* future_a  = (const float*)d_in[3];
    const float* Ws  = (const float*)d_in[4];
    const float* bs  = (const float*)d_in[5];
    const float* Wa  = (const float*)d_in[6];
    const float* ba  = (const float*)d_in[7];
    const float* Wih = (const float*)d_in[8];
    const float* Whh = (const float*)d_in[9];
    const float* bih = (const float*)d_in[10];
    const float* bhh = (const float*)d_in[11];
    const float* Wr  = (const float*)d_in[12];
    const float* br  = (const float*)d_in[13];
    const float* Ws2 = (const float*)d_in[14];
    const float* bs2 = (const float*)d_in[15];

    float* out_r = (float*)d_out;
    float* out_s = (float*)d_out + BB * TFN;

    cudaFuncSetAttribute(mm_kernel, cudaFuncAttributeMaxDynamicSharedMemorySize, SMEM_BYTES);

    float *gi, *gh0b, *gh1b, *gi1b, *h0f, *h1f;
    cudaGetSymbolAddress((void**)&gi,   g_gi);
    cudaGetSymbolAddress((void**)&gh0b, g_gh0);
    cudaGetSymbolAddress((void**)&gh1b, g_gh1);
    cudaGetSymbolAddress((void**)&gi1b, g_gi1);
    cudaGetSymbolAddress((void**)&h0f,  g_h0f);
    cudaGetSymbolAddress((void**)&h1f,  g_h1f);

    __half *xs_h, *h0h, *h1h, *xh, *sh, *hs, *ha, *ps, *fa;
    cudaGetSymbolAddress((void**)&xs_h, g_xs_h);
    cudaGetSymbolAddress((void**)&h0h, g_h0h);
    cudaGetSymbolAddress((void**)&h1h, g_h1h);
    cudaGetSymbolAddress((void**)&xh,  g_xh);
    cudaGetSymbolAddress((void**)&sh,  g_sh);
    cudaGetSymbolAddress((void**)&hs,  g_hs);
    cudaGetSymbolAddress((void**)&ha,  g_ha);
    cudaGetSymbolAddress((void**)&ps,  g_ps);
    cudaGetSymbolAddress((void**)&fa,  g_fa);

    __half *Ws_h, *Ws_l, *Wa_h, *Wa_l, *Wih_h, *Wih_l, *Whh_h, *Whh_l, *Ws2_h, *Ws2_l;
    cudaGetSymbolAddress((void**)&Ws_h,  g_Ws_hi);  cudaGetSymbolAddress((void**)&Ws_l,  g_Ws_lo);
    cudaGetSymbolAddress((void**)&Wa_h,  g_Wa_hi);  cudaGetSymbolAddress((void**)&Wa_l,  g_Wa_lo);
    cudaGetSymbolAddress((void**)&Wih_h, g_Wih_hi); cudaGetSymbolAddress((void**)&Wih_l, g_Wih_lo);
    cudaGetSymbolAddress((void**)&Whh_h, g_Whh_hi); cudaGetSymbolAddress((void**)&Whh_l, g_Whh_lo);
    cudaGetSymbolAddress((void**)&Ws2_h, g_Ws2_hi); cudaGetSymbolAddress((void**)&Ws2_l, g_Ws2_lo);

    auto splitw = [](const float* w, __half* hi, __half* lo, int n) {
        split_w_kernel<<<(n + 255) / 256, 256>>>(w, hi, lo, n);
    };
    auto tohalf = [](const float* w, __half* o, int n) {
        tohalf_kernel<<<(n + 255) / 256, 256>>>(w, o, n);
    };
    splitw(Ws,  Ws_h,  Ws_l,  FS * SS);
    splitw(Wa,  Wa_h,  Wa_l,  FS * AS);
    splitw(Wih, Wih_h, Wih_l, 2 * G3 * FS);
    splitw(Whh, Whh_h, Whh_l, 2 * G3 * FS);
    splitw(Ws2, Ws2_h, Ws2_l, SS * FS);
    tohalf(history_s, hs, BB * THN * SS);
    tohalf(history_a, ha, BB * THN * AS);
    tohalf(present_s, ps, BB * SS);
    tohalf(future_a,  fa, BB * TFN * AS);

    const __half *Wih0h = Wih_h, *Wih0l = Wih_l;
    const __half *Wih1h = Wih_h + (size_t)G3 * FS, *Wih1l = Wih_l + (size_t)G3 * FS;
    const __half *Whh0h = Whh_h, *Whh0l = Whh_l;
    const __half *Whh1h = Whh_h + (size_t)G3 * FS, *Whh1l = Whh_l + (size_t)G3 * FS;
    const float *bih0 = bih, *bih1 = bih + G3, *bhh0 = bhh, *bhh1 = bhh + G3;

    zero_h<<<(BB * FS + 255) / 256, 256>>>(h0f, h1f, h0h, h1h);

    // prefix embeddings -> xs plane [t][b][f] (interleaved; present last)
    mm1(mk(hs, SS, Ws_h, Ws_l, bs, nullptr, 0, xs_h, FS, 1, 1), BB * THN, FS, SS);
    mm1(mk(ha, AS, Wa_h, Wa_l, ba, nullptr, 0, xs_h, FS, 1, 2), BB * THN, FS, AS);
    mm1(mk(ps, SS, Ws_h, Ws_l, bs, nullptr, 0,
           xs_h + (size_t)(TT - 1) * BB * FS, FS, 1, 0), BB, FS, SS);

    // layer-0 input gates for all prefix steps (batched)
    mm1(mk(xs_h, FS, Wih0h, Wih0l, bih0, gi, G3, nullptr, 0, 0, 0), TT * BB, G3, FS);

    auto combine1 = [&](const float* a, const float* b, float* hf, __half* hh) {
        gru_combine2<<<(BB * FS / 2) / 256, 256>>>(a, b, hf, hh,
                                                   nullptr, nullptr, nullptr, nullptr);
    };
    auto combine2 = [&](const float* a0, const float* b0) {
        gru_combine2<<<(BB * FS) / 256, 256>>>(a0, b0, h0f, h0h, gi1b, gh1b, h1f, h1h);
    };

    // interleaved two-layer prefix scan (L1 lags one step behind L0)
    mm1(mk(h0h, FS, Whh0h, Whh0l, bhh0, gh0b, G3, nullptr, 0, 0, 0), BB, G3, FS);
    combine1(gi, gh0b, h0f, h0h);
    for (int tau = 0; tau < TT - 1; tau++) {
        mm3(mk(h0h, FS, Whh0h, Whh0l, bhh0, gh0b, G3, nullptr, 0, 0, 0),
            mk(h0h, FS, Wih1h, Wih1l, bih1, gi1b, G3, nullptr, 0, 0, 0),
            mk(h1h, FS, Whh1h, Whh1l, bhh1, gh1b, G3, nullptr, 0, 0, 0),
            BB, G3, FS);
        combine2(gi + (size_t)(tau + 1) * BB * G3, gh0b);
    }
    mm2(mk(h0h, FS, Wih1h, Wih1l, bih1, gi1b, G3, nullptr, 0, 0, 0),
        mk(h1h, FS, Whh1h, Whh1l, bhh1, gh1b, G3, nullptr, 0, 0, 0),
        BB, G3, FS);
    combine1(gi1b, gh1b, h1f, h1h);

    // future rollout
    for (int t = 0; t < TFN; t++) {
        mm1(mk(fa + (size_t)t * AS, (int64_t)TFN * AS, Wa_h, Wa_l, ba,
               nullptr, 0, xh, FS, 1, 0), BB, FS, AS);
        mm2(mk(xh,  FS, Wih0h, Wih0l, bih0, gi1b, G3, nullptr, 0, 0, 0),
            mk(h0h, FS, Whh0h, Whh0l, bhh0, gh0b, G3, nullptr, 0, 0, 0),
            BB, G3, FS);
        combine1(gi1b, gh0b, h0f, h0h);
        mm2(mk(h0h, FS, Wih1h, Wih1l, bih1, gi1b, G3, nullptr, 0, 0, 0),
            mk(h1h, FS, Whh1h, Whh1l, bhh1, gh1b, G3, nullptr, 0, 0, 0),
            BB, G3, FS);
        combine1(gi1b, gh1b, h1f, h1h);

        reward_kernel<<<(BB * 32 + 255) / 256, 256>>>(h1f, Wr, br, out_r, t);
        mm1(mk(h1h, FS, Ws2_h, Ws2_l, bs2,
               out_s + (size_t)t * SS, (int64_t)TFN * SS, sh, SS, 1, 0),
            BB, SS, FS);
        mm1(mk(sh, SS, Ws_h, Ws_l, bs, nullptr, 0, xh, FS, 1, 0), BB, FS, SS);

        mm2(mk(xh,  FS, Wih0h, Wih0l, bih0, gi1b, G3, nullptr, 0, 0, 0),
            mk(h0h, FS, Whh0h, Whh0l, bhh0, gh0b, G3, nullptr, 0, 0, 0),
            BB, G3, FS);
        combine1(gi1b, gh0b, h0f, h0h);
        mm2(mk(h0h, FS, Wih1h, Wih1l, bih1, gi1b, G3, nullptr, 0, 0, 0),
            mk(h1h, FS, Whh1h, Whh1l, bhh1, gh1b, G3, nullptr, 0, 0, 0),
            BB, G3, FS);
        combine1(gi1b, gh1b, h1f, h1h);
    }
}

// round 14
// speedup vs baseline: 4.0581x; 1.0010x over previous
#include <cuda_runtime.h>
#include <cuda_fp16.h>
#include <cstdint>
#include <math.h>

constexpr int BB  = 256;
constexpr int THN = 32;
constexpr int TFN = 16;
constexpr int SS  = 512;
constexpr int AS  = 128;
constexpr int FS  = 1024;
constexpr int G3  = 3072;
constexpr int TT  = 65;

// ---------------- scratch (device globals; no allocation allowed) ----------
__device__ float g_gi  [TT * BB * G3];     // prefix layer-0 input gates (fp32)
__device__ float g_gia [TFN * BB * G3];    // future action-feed layer-0 gates
__device__ float g_gh0 [BB * G3];
__device__ float g_gh1 [BB * G3];
__device__ float g_gi1 [BB * G3];
__device__ float g_h0f [BB * FS];
__device__ float g_h1f [BB * FS];
__device__ unsigned int g_bar;             // grid barrier counter (scan kernel)

// fp16 activation planes
__device__ __half g_xs_h[TT * BB * FS];
__device__ __half g_xa  [TFN * BB * FS];   // future action embeddings [t][b][f]
__device__ __half g_h0h[BB * FS];
__device__ __half g_h1h[BB * FS];
__device__ __half g_xh [BB * FS];
__device__ __half g_sh [BB * SS];
__device__ __half g_hs [BB * THN * SS];
__device__ __half g_ha [BB * THN * AS];
__device__ __half g_ps [BB * SS];
__device__ __half g_fa [BB * TFN * AS];

// split fp16 weights (hi/lo), laid out [N, K]
__device__ __half g_Ws_hi [FS * SS],     g_Ws_lo [FS * SS];
__device__ __half g_Wa_hi [FS * AS],     g_Wa_lo [FS * AS];
__device__ __half g_Wih_hi[2 * G3 * FS], g_Wih_lo[2 * G3 * FS];
__device__ __half g_Whh_hi[2 * G3 * FS], g_Whh_lo[2 * G3 * FS];
__device__ __half g_Ws2_hi[SS * FS],     g_Ws2_lo[SS * FS];

// ---------------- PTX helpers ----------------------------------------------
__device__ __forceinline__ uint32_t smem_u32(const void* p) {
    uint32_t a;
    asm("{ .reg .u64 t; cvta.to.shared.u64 t, %1; cvt.u32.u64 %0, t; }"
        : "=r"(a) : "l"(p));
    return a;
}

__device__ __forceinline__ void ldmx4(uint32_t* r, uint32_t addr) {
    asm volatile("ldmatrix.sync.aligned.m8n8.x4.shared.b16 {%0,%1,%2,%3}, [%4];"
                 : "=r"(r[0]), "=r"(r[1]), "=r"(r[2]), "=r"(r[3]) : "r"(addr));
}

__device__ __forceinline__ void mma16816(float* d, const uint32_t* a, const uint32_t* b) {
    asm volatile(
        "mma.sync.aligned.m16n8k16.row.col.f32.f16.f16.f32 "
        "{%0,%1,%2,%3}, {%4,%5,%6,%7}, {%8,%9}, {%0,%1,%2,%3};"
        : "+f"(d[0]), "+f"(d[1]), "+f"(d[2]), "+f"(d[3])
        : "r"(a[0]), "r"(a[1]), "r"(a[2]), "r"(a[3]), "r"(b[0]), "r"(b[1]));
}

__device__ __forceinline__ void cpasync16(uint32_t dst, const void* src) {
    asm volatile("cp.async.cg.shared.global [%0], [%1], 16;" :: "r"(dst), "l"(src));
}
#define CP_COMMIT()  asm volatile("cp.async.commit_group;")
#define CP_WAIT1()   asm volatile("cp.async.wait_group 1;")
#define CP_WAIT0()   asm volatile("cp.async.wait_group 0;")

constexpr int ST_A  = 0;
constexpr int ST_WH = 16384;
constexpr int ST_WL = 32768;
constexpr int STAGE = 49152;
constexpr int SMEM_BYTES = 98304;

__device__ __forceinline__ float act_f(float v, int act) {
    if (act == 1) return tanhf(v);
    if (act == 2) return 1.0f / (1.0f + expf(-v));
    return v;
}

// ---------------- shared GEMM tile core -------------------------------------
// Computes 128x128 fp32 tile: acc = sum_k A[m,k]*(Wh[n,k]+Wl[n,k]) (2-pass fp16)
__device__ __forceinline__ void issue_stage_p(
    const __half* A, int64_t lda, const __half* Wh, const __half* Wl,
    int K, int row0, int col0, int k0, uint32_t sbase, int tid)
{
    const int row  = tid >> 1;
    const int colb = (tid & 1) * 64;
    const int cole = colb >> 1;
    const uint32_t dbase  = (uint32_t)(row * 128);
    const uint32_t swmask = (uint32_t)((row & 7) << 4);
    const __half* a_p = A  + (size_t)(row0 + row) * lda + k0 + cole;
    const __half* w_h = Wh + (size_t)(col0 + row) * K + k0 + cole;
    const __half* w_l = Wl + (size_t)(col0 + row) * K + k0 + cole;
    #pragma unroll
    for (int j = 0; j < 4; j++) {
        uint32_t sw = (dbase + (uint32_t)(colb + j * 16)) ^ swmask;
        cpasync16(sbase + ST_A  + sw, a_p + j * 8);
        cpasync16(sbase + ST_WH + sw, w_h + j * 8);
        cpasync16(sbase + ST_WL + sw, w_l + j * 8);
    }
}

__device__ __forceinline__ void gemm128_acc(
    const __half* A, int64_t lda, const __half* Wh, const __half* Wl,
    int K, int row0, int col0, uint32_t sb, int tid, int m0w, int n0w, int lane,
    float acc[4][4][4])
{
    const int NC = K >> 6;
    issue_stage_p(A, lda, Wh, Wl, K, row0, col0, 0, sb, tid);
    CP_COMMIT();
    if (NC > 1) { issue_stage_p(A, lda, Wh, Wl, K, row0, col0, 64, sb + STAGE, tid); CP_COMMIT(); }

    #pragma unroll
    for (int i = 0; i < 4; i++)
        #pragma unroll
        for (int j = 0; j < 4; j++)
            #pragma unroll
            for (int q = 0; q < 4; q++) acc[i][j][q] = 0.0f;

    const uint32_t a_lrow  = (uint32_t)(lane & 15);
    const uint32_t a_lcolb = (uint32_t)((lane >> 4) * 16);
    const uint32_t b_lrow  = (uint32_t)((lane & 7) + ((lane >> 4) & 1) * 8);
    const uint32_t b_lcolb = (uint32_t)(((lane >> 3) & 1) * 16);

    for (int c = 0; c < NC; c++) {
        if (c + 1 < NC) { CP_WAIT1(); } else { CP_WAIT0(); }
        __syncthreads();
        const uint32_t st = sb + (uint32_t)((c & 1) * STAGE);

        #pragma unroll
        for (int ks = 0; ks < 4; ks++) {
            const uint32_t kc = (uint32_t)(ks * 32);
            uint32_t Af[16], Bh[8], Bl[8];
            #pragma unroll
            for (int mt = 0; mt < 4; mt++) {
                uint32_t r = (uint32_t)(m0w + mt * 16) + a_lrow;
                uint32_t off = r * 128 + ((kc + a_lcolb) ^ ((r & 7) << 4));
                ldmx4(Af + mt * 4, st + ST_A + off);
            }
            #pragma unroll
            for (int p = 0; p < 2; p++) {
                uint32_t r = (uint32_t)(n0w + p * 16) + b_lrow;
                uint32_t off = r * 128 + ((kc + b_lcolb) ^ ((r & 7) << 4));
                ldmx4(Bh + p * 4, st + ST_WH + off);
                ldmx4(Bl + p * 4, st + ST_WL + off);
            }
            #pragma unroll
            for (int mt = 0; mt < 4; mt++) {
                #pragma unroll
                for (int nt = 0; nt < 4; nt++) {
                    const uint32_t* bh = &Bh[(nt >> 1) * 4 + (nt & 1) * 2];
                    const uint32_t* bl = &Bl[(nt >> 1) * 4 + (nt & 1) * 2];
                    mma16816(acc[mt][nt], Af + mt * 4, bh);
                    mma16816(acc[mt][nt], Af + mt * 4, bl);
                }
            }
        }
        __syncthreads();
        if (c + 2 < NC) {
            issue_stage_p(A, lda, Wh, Wl, K, row0, col0, (c + 2) << 6,
                          sb + (uint32_t)((c & 1) * STAGE), tid);
            CP_COMMIT();
        }
    }
}

// ---------------- general GEMM kernel ---------------------------------------
struct GTask {
    const __half* A; int64_t lda;
    const __half *Wh, *Wl;
    const float* bias;
    float* Cf; int64_t ldcf;           // optional fp32 output
    __half* Ch; int64_t ldch;          // optional fp16 plane output
    int act; int rowmap;
};

__global__ void __launch_bounds__(256, 1) mm_kernel(GTask T0, GTask T1, GTask T2, int K)
{
    extern __shared__ __align__(16) char sm[];
    const GTask T = (blockIdx.z == 0) ? T0 : (blockIdx.z == 1 ? T1 : T2);
    const uint32_t sb = smem_u32(sm);
    const int tid  = threadIdx.x;
    const int wid  = tid >> 5, lane = tid & 31;
    const int row0 = blockIdx.y * 128, col0 = blockIdx.x * 128;
    const int m0w  = (wid >> 2) * 64;
    const int n0w  = (wid & 3) * 32;

    float acc[4][4][4];
    gemm128_acc(T.A, T.lda, T.Wh, T.Wl, K, row0, col0, sb, tid, m0w, n0w, lane, acc);

    const int tq = lane >> 2, tr = lane & 3;
    #pragma unroll
    for (int mt = 0; mt < 4; mt++) {
        #pragma unroll
        for (int half = 0; half < 2; half++) {
            int m = row0 + m0w + mt * 16 + half * 8 + tq;
            int mp;
            if (T.rowmap == 1)      mp = ((m & 31) << 1) * BB + (m >> 5);
            else if (T.rowmap == 2) mp = (((m & 31) << 1) + 1) * BB + (m >> 5);
            else if (T.rowmap == 3) mp = (m & 15) * BB + (m >> 4);
            else                    mp = m;
            float* cf = T.Cf ? T.Cf + (size_t)mp * T.ldcf : nullptr;
            __half* ch = T.Ch ? T.Ch + (size_t)mp * T.ldch : nullptr;
            #pragma unroll
            for (int nt = 0; nt < 4; nt++) {
                int n = col0 + n0w + nt * 8 + tr * 2;
                float2 bv = *(const float2*)(T.bias + n);
                float vx = act_f(acc[mt][nt][half * 2 + 0] + bv.x, T.act);
                float vy = act_f(acc[mt][nt][half * 2 + 1] + bv.y, T.act);
                if (cf) { float2 o; o.x = vx; o.y = vy; *(float2*)(cf + n) = o; }
                if (ch) {
                    uint32_t hp = (uint32_t)__half_as_ushort(__float2half_rn(vx))
                                | ((uint32_t)__half_as_ushort(__float2half_rn(vy)) << 16);
                    *(uint32_t*)(ch + n) = hp;
                }
            }
        }
    }
}

// ---------------- persistent scan kernel -------------------------------------
// 144 CTAs (1/SM, single wave). 66 phases: GEMM -> bar -> combine -> bar.
// Cross-CTA data crosses barriers via L2 only (cp.async.cg / __ldcg / st WT).
__device__ __forceinline__ void grid_bar(unsigned target) {
    __syncthreads();
    if (threadIdx.x == 0) {
        __threadfence();
        atomicAdd(&g_bar, 1u);
        unsigned v;
        do {
            asm volatile("ld.global.cg.u32 %0, [%1];" : "=r"(v) : "l"(&g_bar));
            if (v < target) __nanosleep(64);
        } while (v < target);
    }
    __syncthreads();
}

__global__ void __launch_bounds__(256, 1) scan_kernel(
    float* h0f, float* h1f, __half* h0h, __half* h1h,
    const __half* Whh0h, const __half* Whh0l,
    const __half* Wih1h, const __half* Wih1l,
    const __half* Whh1h, const __half* Whh1l,
    const float* bhh0, const float* bih1, const float* bhh1,
    const float* gi, float* gh0b, float* gi1b, float* gh1b)
{
    extern __shared__ __align__(16) char sm[];
    const uint32_t sb = smem_u32(sm);
    const int tid  = threadIdx.x;
    const int wid  = tid >> 5, lane = tid & 31;
    const int m0w  = (wid >> 2) * 64;
    const int n0w  = (wid & 3) * 32;

    const int cta = blockIdx.x;
    const int mat = cta % 3;          // 0: gh0, 1: gi1, 2: gh1
    const int tilid = cta / 3;        // 0..47
    const int col0 = (tilid % 24) * 128;
    const int row0 = (tilid / 24) * 128;

    const __half* Asrc; const __half *Wh, *Wl; const float* bias; float* Cout;
    if (mat == 0)      { Asrc = h0h; Wh = Whh0h; Wl = Whh0l; bias = bhh0; Cout = gh0b; }
    else if (mat == 1) { Asrc = h0h; Wh = Wih1h; Wl = Wih1l; bias = bih1; Cout = gi1b; }
    else               { Asrc = h1h; Wh = Whh1h; Wl = Whh1l; bias = bhh1; Cout = gh1b; }

    const int gtid = cta * 256 + tid;
    constexpr int NT = 144 * 256;
    constexpr int NP = BB * FS / 2;
    const int tq = lane >> 2, tr = lane & 3;

    unsigned epoch = 0;

    for (int it = 0; it < TT + 1; it++) {
        const bool do_gemm = (mat == 0) ? (it <= TT - 1) : (it >= 1);
        if (do_gemm) {
            float acc[4][4][4];
            gemm128_acc(Asrc, FS, Wh, Wl, FS, row0, col0, sb, tid, m0w, n0w, lane, acc);
            #pragma unroll
            for (int mt = 0; mt < 4; mt++) {
                #pragma unroll
                for (int half = 0; half < 2; half++) {
                    int m = row0 + m0w + mt * 16 + half * 8 + tq;
                    float* cf = Cout + (size_t)m * G3;
                    #pragma unroll
                    for (int nt = 0; nt < 4; nt++) {
                        int n = col0 + n0w + nt * 8 + tr * 2;
                        float2 bv = *(const float2*)(bias + n);
                        float2 o;
                        o.x = acc[mt][nt][half * 2 + 0] + bv.x;
                        o.y = acc[mt][nt][half * 2 + 1] + bv.y;
                        *(float2*)(cf + n) = o;
                    }
                }
            }
        }
        grid_bar(++epoch * 144u);

        // combine: L0 uses gi[it] + gh0b (if it<=64); L1 uses gi1b + gh1b (if it>=1)
        if (it <= TT - 1) {
            const float* gi0 = gi + (size_t)it * BB * G3;
            for (int p = gtid; p < NP; p += NT) {
                int m = p >> 9, j = (p & 511) << 1;
                size_t base = (size_t)m * G3 + j;
                float2 ir = *(const float2*)(gi0 + base);
                float2 iz = *(const float2*)(gi0 + base + FS);
                float2 in = *(const float2*)(gi0 + base + 2 * FS);
                float2 hr = __ldcg((const float2*)(gh0b + base));
                float2 hz = __ldcg((const float2*)(gh0b + base + FS));
                float2 hn = __ldcg((const float2*)(gh0b + base + 2 * FS));
                int hidx = m * FS + j;
                float2 hold = *(const float2*)(h0f + hidx);
                float r0 = 1.0f / (1.0f + expf(-(ir.x + hr.x)));
                float z0 = 1.0f / (1.0f + expf(-(iz.x + hz.x)));
                float n0 = tanhf(in.x + r0 * hn.x);
                float v0 = (1.0f - z0) * n0 + z0 * hold.x;
                float r1 = 1.0f / (1.0f + expf(-(ir.y + hr.y)));
                float z1 = 1.0f / (1.0f + expf(-(iz.y + hz.y)));
                float n1 = tanhf(in.y + r1 * hn.y);
                float v1 = (1.0f - z1) * n1 + z1 * hold.y;
                float2 o; o.x = v0; o.y = v1;
                *(float2*)(h0f + hidx) = o;
                uint32_t hp = (uint32_t)__half_as_ushort(__float2half_rn(v0))
                            | ((uint32_t)__half_as_ushort(__float2half_rn(v1)) << 16);
                *(uint32_t*)(h0h + hidx) = hp;
            }
        }
        if (it >= 1) {
            for (int p = gtid; p < NP; p += NT) {
                int m = p >> 9, j = (p & 511) << 1;
                size_t base = (size_t)m * G3 + j;
                float2 ir = __ldcg((const float2*)(gi1b + base));
                float2 iz = __ldcg((const float2*)(gi1b + base + FS));
                float2 in = __ldcg((const float2*)(gi1b + base + 2 * FS));
                float2 hr = __ldcg((const float2*)(gh1b + base));
                float2 hz = __ldcg((const float2*)(gh1b + base + FS));
                float2 hn = __ldcg((const float2*)(gh1b + base + 2 * FS));
                int hidx = m * FS + j;
                float2 hold = *(const float2*)(h1f + hidx);
                float r0 = 1.0f / (1.0f + expf(-(ir.x + hr.x)));
                float z0 = 1.0f / (1.0f + expf(-(iz.x + hz.x)));
                float n0 = tanhf(in.x + r0 * hn.x);
                float v0 = (1.0f - z0) * n0 + z0 * hold.x;
                float r1 = 1.0f / (1.0f + expf(-(ir.y + hr.y)));
                float z1 = 1.0f / (1.0f + expf(-(iz.y + hz.y)));
                float n1 = tanhf(in.y + r1 * hn.y);
                float v1 = (1.0f - z1) * n1 + z1 * hold.y;
                float2 o; o.x = v0; o.y = v1;
                *(float2*)(h1f + hidx) = o;
                uint32_t hp = (uint32_t)__half_as_ushort(__float2half_rn(v0))
                            | ((uint32_t)__half_as_ushort(__float2half_rn(v1)) << 16);
                *(uint32_t*)(h1h + hidx) = hp;
            }
        }
        grid_bar(++epoch * 144u);
    }
}

// ---------------- elementwise kernels --------------------------------------
__global__ void split_w_kernel(const float* __restrict__ w,
                               __half* __restrict__ hi,
                               __half* __restrict__ lo, int n)
{
    int i = blockIdx.x * blockDim.x + threadIdx.x;
    if (i < n) {
        float v = w[i];
        __half h = __float2half_rn(v);
        hi[i] = h;
        lo[i] = __float2half_rn(v - __half2float(h));
    }
}

__global__ void tohalf_kernel(const float* __restrict__ w,
                              __half* __restrict__ o, int n)
{
    int i = blockIdx.x * blockDim.x + threadIdx.x;
    if (i < n) o[i] = __float2half_rn(w[i]);
}

__global__ void gru_combine1(
    const float* __restrict__ gi0, const float* __restrict__ gh0,
    float* __restrict__ hf, __half* __restrict__ hh)
{
    int p = blockIdx.x * blockDim.x + threadIdx.x;
    int m = p >> 9;
    int j = (p & 511) * 2;
    size_t base = (size_t)m * G3 + j;
    float2 ir = *(const float2*)(gi0 + base);
    float2 iz = *(const float2*)(gi0 + base + FS);
    float2 in = *(const float2*)(gi0 + base + 2 * FS);
    float2 hr = *(const float2*)(gh0 + base);
    float2 hz = *(const float2*)(gh0 + base + FS);
    float2 hn = *(const float2*)(gh0 + base + 2 * FS);
    int hidx = m * FS + j;
    float2 hold = *(const float2*)(hf + hidx);

    float r0 = 1.0f / (1.0f + expf(-(ir.x + hr.x)));
    float z0 = 1.0f / (1.0f + expf(-(iz.x + hz.x)));
    float n0 = tanhf(in.x + r0 * hn.x);
    float v0 = (1.0f - z0) * n0 + z0 * hold.x;
    float r1 = 1.0f / (1.0f + expf(-(ir.y + hr.y)));
    float z1 = 1.0f / (1.0f + expf(-(iz.y + hz.y)));
    float n1 = tanhf(in.y + r1 * hn.y);
    float v1 = (1.0f - z1) * n1 + z1 * hold.y;

    float2 o; o.x = v0; o.y = v1;
    *(float2*)(hf + hidx) = o;
    uint32_t hp = (uint32_t)__half_as_ushort(__float2half_rn(v0))
                | ((uint32_t)__half_as_ushort(__float2half_rn(v1)) << 16);
    *(uint32_t*)(hh + hidx) = hp;
}

__global__ void reward_kernel(const float* __restrict__ h1,
                              const float* __restrict__ Wr,
                              const float* __restrict__ br,
                              float* __restrict__ out_r, int t)
{
    int g = blockIdx.x * blockDim.x + threadIdx.x;
    int warp = g >> 5, lane = g & 31;
    if (warp >= BB) return;
    const float* hr = h1 + (size_t)warp * FS;
    float s = 0.0f;
    #pragma unroll 8
    for (int k = lane; k < FS; k += 32) s += hr[k] * Wr[k];
    #pragma unroll
    for (int o = 16; o; o >>= 1) s += __shfl_xor_sync(0xFFFFFFFFu, s, o);
    if (lane == 0)
        out_r[warp * TFN + t] = 1.0f / (1.0f + expf(-(s + br[0])));
}

__global__ void zero_h(float* __restrict__ a, float* __restrict__ b,
                       __half* __restrict__ ah, __half* __restrict__ bh)
{
    int idx = blockIdx.x * blockDim.x + threadIdx.x;
    if (idx == 0) g_bar = 0u;
    if (idx < BB * FS) {
        a[idx] = 0.0f; b[idx] = 0.0f;
        ah[idx] = __float2half(0.0f); bh[idx] = __float2half(0.0f);
    }
}

// ---------------- host orchestration ---------------------------------------
static GTask mk(const __half* A, int64_t lda,
                const __half* Wh, const __half* Wl, const float* bias,
                float* Cf, int64_t ldcf, __half* Ch, int64_t ldch,
                int act, int rowmap)
{
    GTask t; t.A = A; t.lda = lda; t.Wh = Wh; t.Wl = Wl; t.bias = bias;
    t.Cf = Cf; t.ldcf = ldcf; t.Ch = Ch; t.ldch = ldch;
    t.act = act; t.rowmap = rowmap;
    return t;
}

static void mm1(const GTask& a, int M, int N, int K) {
    dim3 g(N / 128, M / 128, 1);
    mm_kernel<<<g, 256, SMEM_BYTES>>>(a, a, a, K);
}
static void mm2(const GTask& a, const GTask& b, int M, int N, int K) {
    dim3 g(N / 128, M / 128, 2);
    mm_kernel<<<g, 256, SMEM_BYTES>>>(a, b, a, K);
}

extern "C" void kernel_launch(void* const* d_in, const int* in_sizes, int n_in,
                              void* d_out, int out_size)
{
    const float* history_s = (const float*)d_in[0];
    const float* history_a = (const float*)d_in[1];
    const float* present_s = (const float*)d_in[2];
    const float* future_a  = (const float*)d_in[3];
    const float* Ws  = (const float*)d_in[4];
    const float* bs  = (const float*)d_in[5];
    const float* Wa  = (const float*)d_in[6];
    const float* ba  = (const float*)d_in[7];
    const float* Wih = (const float*)d_in[8];
    const float* Whh = (const float*)d_in[9];
    const float* bih = (const float*)d_in[10];
    const float* bhh = (const float*)d_in[11];
    const float* Wr  = (const float*)d_in[12];
    const float* br  = (const float*)d_in[13];
    const float* Ws2 = (const float*)d_in[14];
    const float* bs2 = (const float*)d_in[15];

    float* out_r = (float*)d_out;
    float* out_s = (float*)d_out + BB * TFN;

    cudaFuncSetAttribute(mm_kernel,   cudaFuncAttributeMaxDynamicSharedMemorySize, SMEM_BYTES);
    cudaFuncSetAttribute(scan_kernel, cudaFuncAttributeMaxDynamicSharedMemorySize, SMEM_BYTES);

    float *gi, *gia, *gh0b, *gh1b, *gi1b, *h0f, *h1f;
    cudaGetSymbolAddress((void**)&gi,   g_gi);
    cudaGetSymbolAddress((void**)&gia,  g_gia);
    cudaGetSymbolAddress((void**)&gh0b, g_gh0);
    cudaGetSymbolAddress((void**)&gh1b, g_gh1);
    cudaGetSymbolAddress((void**)&gi1b, g_gi1);
    cudaGetSymbolAddress((void**)&h0f,  g_h0f);
    cudaGetSymbolAddress((void**)&h1f,  g_h1f);

    __half *xs_h, *xa, *h0h, *h1h, *xh, *sh, *hs, *ha, *ps, *fa;
    cudaGetSymbolAddress((void**)&xs_h, g_xs_h);
    cudaGetSymbolAddress((void**)&xa,  g_xa);
    cudaGetSymbolAddress((void**)&h0h, g_h0h);
    cudaGetSymbolAddress((void**)&h1h, g_h1h);
    cudaGetSymbolAddress((void**)&xh,  g_xh);
    cudaGetSymbolAddress((void**)&sh,  g_sh);
    cudaGetSymbolAddress((void**)&hs,  g_hs);
    cudaGetSymbolAddress((void**)&ha,  g_ha);
    cudaGetSymbolAddress((void**)&ps,  g_ps);
    cudaGetSymbolAddress((void**)&fa,  g_fa);

    __half *Ws_h, *Ws_l, *Wa_h, *Wa_l, *Wih_h, *Wih_l, *Whh_h, *Whh_l, *Ws2_h, *Ws2_l;
    cudaGetSymbolAddress((void**)&Ws_h,  g_Ws_hi);  cudaGetSymbolAddress((void**)&Ws_l,  g_Ws_lo);
    cudaGetSymbolAddress((void**)&Wa_h,  g_Wa_hi);  cudaGetSymbolAddress((void**)&Wa_l,  g_Wa_lo);
    cudaGetSymbolAddress((void**)&Wih_h, g_Wih_hi); cudaGetSymbolAddress((void**)&Wih_l, g_Wih_lo);
    cudaGetSymbolAddress((void**)&Whh_h, g_Whh_hi); cudaGetSymbolAddress((void**)&Whh_l, g_Whh_lo);
    cudaGetSymbolAddress((void**)&Ws2_h, g_Ws2_hi); cudaGetSymbolAddress((void**)&Ws2_l, g_Ws2_lo);

    auto splitw = [](const float* w, __half* hi, __half* lo, int n) {
        split_w_kernel<<<(n + 255) / 256, 256>>>(w, hi, lo, n);
    };
    auto tohalf = [](const float* w, __half* o, int n) {
        tohalf_kernel<<<(n + 255) / 256, 256>>>(w, o, n);
    };
    splitw(Ws,  Ws_h,  Ws_l,  FS * SS);
    splitw(Wa,  Wa_h,  Wa_l,  FS * AS);
    splitw(Wih, Wih_h, Wih_l, 2 * G3 * FS);
    splitw(Whh, Whh_h, Whh_l, 2 * G3 * FS);
    splitw(Ws2, Ws2_h, Ws2_l, SS * FS);
    tohalf(history_s, hs, BB * THN * SS);
    tohalf(history_a, ha, BB * THN * AS);
    tohalf(present_s, ps, BB * SS);
    tohalf(future_a,  fa, BB * TFN * AS);

    const __half *Wih0h = Wih_h, *Wih0l = Wih_l;
    const __half *Wih1h = Wih_h + (size_t)G3 * FS, *Wih1l = Wih_l + (size_t)G3 * FS;
    const __half *Whh0h = Whh_h, *Whh0l = Whh_l;
    const __half *Whh1h = Whh_h + (size_t)G3 * FS, *Whh1l = Whh_l + (size_t)G3 * FS;
    const float *bih0 = bih, *bih1 = bih + G3, *bhh0 = bhh, *bhh1 = bhh + G3;

    zero_h<<<(BB * FS + 255) / 256, 256>>>(h0f, h1f, h0h, h1h);

    // prefix embeddings -> xs plane [t][b][f] (interleaved; present last)
    mm1(mk(hs, SS, Ws_h, Ws_l, bs, nullptr, 0, xs_h, FS, 1, 1), BB * THN, FS, SS);
    mm1(mk(ha, AS, Wa_h, Wa_l, ba, nullptr, 0, xs_h, FS, 1, 2), BB * THN, FS, AS);
    mm1(mk(ps, SS, Ws_h, Ws_l, bs, nullptr, 0,
           xs_h + (size_t)(TT - 1) * BB * FS, FS, 1, 0), BB, FS, SS);

    // batched: layer-0 prefix input gates; future action embeddings + their gates
    mm1(mk(xs_h, FS, Wih0h, Wih0l, bih0, gi, G3, nullptr, 0, 0, 0), TT * BB, G3, FS);
    mm1(mk(fa, AS, Wa_h, Wa_l, ba, nullptr, 0, xa, FS, 1, 3), BB * TFN, FS, AS);
    mm1(mk(xa, FS, Wih0h, Wih0l, bih0, gia, G3, nullptr, 0, 0, 0), TFN * BB, G3, FS);

    // ---- persistent two-layer prefix scan (66 phases, one launch) ----
    scan_kernel<<<144, 256, SMEM_BYTES>>>(
        h0f, h1f, h0h, h1h,
        Whh0h, Whh0l, Wih1h, Wih1l, Whh1h, Whh1l,
        bhh0, bih1, bhh1, gi, gh0b, gi1b, gh1b);

    auto combine = [&](const float* a, const float* b, float* hf, __half* hh) {
        gru_combine1<<<(BB * FS / 2) / 256, 256>>>(a, b, hf, hh);
    };

    // ---- future rollout ----
    for (int t = 0; t < TFN; t++) {
        // cell 0 (action input; gates precomputed in gia)
        mm1(mk(h0h, FS, Whh0h, Whh0l, bhh0, gh0b, G3, nullptr, 0, 0, 0), BB, G3, FS);
        combine(gia + (size_t)t * BB * G3, gh0b, h0f, h0h);
        mm2(mk(h0h, FS, Wih1h, Wih1l, bih1, gi1b, G3, nullptr, 0, 0, 0),
            mk(h1h, FS, Whh1h, Whh1l, bhh1, gh1b, G3, nullptr, 0, 0, 0),
            BB, G3, FS);
        combine(gi1b, gh1b, h1f, h1h);

        reward_kernel<<<(BB * 32 + 255) / 256, 256>>>(h1f, Wr, br, out_r, t);
        mm1(mk(h1h, FS, Ws2_h, Ws2_l, bs2,
               out_s + (size_t)t * SS, (int64_t)TFN * SS, sh, SS, 1, 0),
            BB, SS, FS);
        mm1(mk(sh, SS, Ws_h, Ws_l, bs, nullptr, 0, xh, FS, 1, 0), BB, FS, SS);

        mm2(mk(xh,  FS, Wih0h, Wih0l, bih0, gi1b, G3, nullptr, 0, 0, 0),
            mk(h0h, FS, Whh0h, Whh0l, bhh0, gh0b, G3, nullptr, 0, 0, 0),
            BB, G3, FS);
        combine(gi1b, gh0b, h0f, h0h);
        mm2(mk(h0h, FS, Wih1h, Wih1l, bih1, gi1b, G3, nullptr, 0, 0, 0),
            mk(h1h, FS, Whh1h, Whh1l, bhh1, gh1b, G3, nullptr, 0, 0, 0),
            BB, G3, FS);
        combine(gi1b, gh1b, h1f, h1h);
    }
}